// round 1
// baseline (speedup 1.0000x reference)
#include <cuda_runtime.h>
#include <math.h>
#include <float.h>

#define NB    8
#define TLEN  4096
#define DM    128
#define HD    64
#define BM    64
#define BN    64
#define TSTR  68   // padded smem row stride (floats), keeps 16B alignment

// Scratch for Q/K/V projections (no allocation allowed in kernel_launch)
__device__ float g_Q[NB * TLEN * HD];
__device__ float g_K[NB * TLEN * HD];
__device__ float g_V[NB * TLEN * HD];

// ---------------------------------------------------------------------------
// QKV projection: one block = 64 rows of x; computes Q|K|V (192 output cols).
// Xts: x tile transposed [128][68] (k-major), Ws: fused W [128][192].
// Thread (ty,tx): 4 rows x 12 cols register tile.
// ---------------------------------------------------------------------------
__global__ __launch_bounds__(256) void qkv_kernel(
    const float* __restrict__ x,
    const float* __restrict__ Wq,
    const float* __restrict__ Wk,
    const float* __restrict__ Wv)
{
    extern __shared__ float sm[];
    float* Xts = sm;             // [128][TSTR]
    float* Ws  = sm + 128 * TSTR; // [128][192]

    const int tid  = threadIdx.x;
    const int row0 = blockIdx.x * 64;

    // load X tile transposed (coalesced global reads)
    const float* xg = x + (size_t)row0 * DM;
    #pragma unroll
    for (int idx = tid; idx < 64 * 128; idx += 256) {
        int r = idx >> 7;          // 0..63
        int k = idx & 127;         // 0..127
        Xts[k * TSTR + r] = xg[r * DM + k];
    }
    // load fused W [128][192]
    for (int idx = tid; idx < 128 * 192; idx += 256) {
        int k = idx / 192;
        int c = idx - k * 192;
        float w;
        if (c < 64)        w = Wq[k * 64 + c];
        else if (c < 128)  w = Wk[k * 64 + (c - 64)];
        else               w = Wv[k * 64 + (c - 128)];
        Ws[k * 192 + c] = w;
    }
    __syncthreads();

    const int ty = tid >> 4, tx = tid & 15;
    const int r0 = ty * 4;
    const int c0 = tx * 12;

    float acc[4][12];
    #pragma unroll
    for (int i = 0; i < 4; i++)
        #pragma unroll
        for (int j = 0; j < 12; j++) acc[i][j] = 0.f;

    #pragma unroll 8
    for (int k = 0; k < 128; k++) {
        float4 xv = *(const float4*)&Xts[k * TSTR + r0];
        float4 w0 = *(const float4*)&Ws[k * 192 + c0];
        float4 w1 = *(const float4*)&Ws[k * 192 + c0 + 4];
        float4 w2 = *(const float4*)&Ws[k * 192 + c0 + 8];
        float xr[4] = {xv.x, xv.y, xv.z, xv.w};
        float wr[12] = {w0.x, w0.y, w0.z, w0.w,
                        w1.x, w1.y, w1.z, w1.w,
                        w2.x, w2.y, w2.z, w2.w};
        #pragma unroll
        for (int i = 0; i < 4; i++)
            #pragma unroll
            for (int j = 0; j < 12; j++)
                acc[i][j] = fmaf(xr[i], wr[j], acc[i][j]);
    }

    // scatter to g_Q / g_K / g_V
    #pragma unroll
    for (int i = 0; i < 4; i++) {
        int row = row0 + r0 + i;
        #pragma unroll
        for (int j = 0; j < 12; j++) {
            int c = c0 + j;
            float v = acc[i][j];
            if (c < 64)        g_Q[(size_t)row * HD + c]         = v;
            else if (c < 128)  g_K[(size_t)row * HD + (c - 64)]  = v;
            else               g_V[(size_t)row * HD + (c - 128)] = v;
        }
    }
}

// ---------------------------------------------------------------------------
// Causal flash attention. Block = (q-tile of 64 rows, batch). 256 threads.
// Qts/Kts stored h-major ([h][r] / [h][c]); Vs [c][h]; Pts [c][r].
// Thread (ty,tx): S micro-tile rows ty*4.., cols tx*4.. ; O micro-tile
// rows ty*4.., head-cols tx*4.. . Online softmax per row, reductions via
// shfl across the 16 tx lanes (contiguous in the warp).
// ---------------------------------------------------------------------------
__global__ __launch_bounds__(256) void attn_kernel(float* __restrict__ Out)
{
    extern __shared__ float sm[];
    float* Qts = sm;                 // [64][TSTR]
    float* Kts = sm + 1 * 64 * TSTR; // [64][TSTR]
    float* Vs  = sm + 2 * 64 * TSTR; // [64][TSTR]
    float* Pts = sm + 3 * 64 * TSTR; // [64][TSTR]

    const int qb  = blockIdx.x;
    const int b   = blockIdx.y;
    const int tid = threadIdx.x;
    const int ty  = tid >> 4, tx = tid & 15;
    const int r0  = ty * 4;
    const float SCALE = 0.08838834764831845f; // 1/sqrt(128)

    const float* Qg = g_Q + ((size_t)b * TLEN + (size_t)qb * BM) * HD;
    #pragma unroll
    for (int idx = tid; idx < BM * HD; idx += 256) {
        int r = idx >> 6, h = idx & 63;
        Qts[h * TSTR + r] = Qg[r * HD + h];
    }

    float m[4], l[4], o[4][4];
    #pragma unroll
    for (int i = 0; i < 4; i++) {
        m[i] = -FLT_MAX; l[i] = 0.f;
        #pragma unroll
        for (int j = 0; j < 4; j++) o[i][j] = 0.f;
    }
    __syncthreads();

    for (int kb = 0; kb <= qb; kb++) {
        const float* Kg = g_K + ((size_t)b * TLEN + (size_t)kb * BN) * HD;
        const float* Vg = g_V + ((size_t)b * TLEN + (size_t)kb * BN) * HD;

        __syncthreads();  // protect Kts/Vs/Pts from previous iteration readers
        #pragma unroll
        for (int idx = tid; idx < BN * HD; idx += 256) {
            int c = idx >> 6, h = idx & 63;
            Kts[h * TSTR + c] = Kg[c * HD + h];
            Vs[c * TSTR + h]  = Vg[c * HD + h];
        }
        __syncthreads();

        const int c0 = tx * 4;
        float s[4][4];
        #pragma unroll
        for (int i = 0; i < 4; i++)
            #pragma unroll
            for (int j = 0; j < 4; j++) s[i][j] = 0.f;

        #pragma unroll 16
        for (int h = 0; h < 64; h++) {
            float4 qv = *(const float4*)&Qts[h * TSTR + r0];
            float4 kv = *(const float4*)&Kts[h * TSTR + c0];
            float qr[4] = {qv.x, qv.y, qv.z, qv.w};
            float kr[4] = {kv.x, kv.y, kv.z, kv.w};
            #pragma unroll
            for (int i = 0; i < 4; i++)
                #pragma unroll
                for (int j = 0; j < 4; j++)
                    s[i][j] = fmaf(qr[i], kr[j], s[i][j]);
        }

        const bool diag = (kb == qb);
        #pragma unroll
        for (int i = 0; i < 4; i++)
            #pragma unroll
            for (int j = 0; j < 4; j++) {
                float v = s[i][j] * SCALE;
                if (diag && (c0 + j) > (r0 + i)) v = -FLT_MAX;
                s[i][j] = v;
            }

        // online softmax per row
        #pragma unroll
        for (int i = 0; i < 4; i++) {
            float rm = fmaxf(fmaxf(s[i][0], s[i][1]), fmaxf(s[i][2], s[i][3]));
            #pragma unroll
            for (int off = 8; off >= 1; off >>= 1)
                rm = fmaxf(rm, __shfl_xor_sync(0xffffffffu, rm, off));
            float mn    = fmaxf(m[i], rm);
            float alpha = __expf(m[i] - mn);
            m[i] = mn;
            float rs = 0.f;
            #pragma unroll
            for (int j = 0; j < 4; j++) {
                float p = __expf(s[i][j] - mn);
                s[i][j] = p;
                rs += p;
            }
            #pragma unroll
            for (int off = 8; off >= 1; off >>= 1)
                rs += __shfl_xor_sync(0xffffffffu, rs, off);
            l[i] = l[i] * alpha + rs;
            #pragma unroll
            for (int j = 0; j < 4; j++) o[i][j] *= alpha;
        }

        // write P transposed: Pts[c][r]
        #pragma unroll
        for (int j = 0; j < 4; j++) {
            float4 pv = make_float4(s[0][j], s[1][j], s[2][j], s[3][j]);
            *(float4*)&Pts[(c0 + j) * TSTR + r0] = pv;
        }
        __syncthreads();

        // O += P @ V  (thread covers rows r0.., head cols tx*4..)
        const int h0 = tx * 4;
        #pragma unroll 16
        for (int c = 0; c < BN; c++) {
            float4 pv = *(const float4*)&Pts[c * TSTR + r0];
            float4 vv = *(const float4*)&Vs[c * TSTR + h0];
            float pr[4] = {pv.x, pv.y, pv.z, pv.w};
            float vr[4] = {vv.x, vv.y, vv.z, vv.w};
            #pragma unroll
            for (int i = 0; i < 4; i++)
                #pragma unroll
                for (int j = 0; j < 4; j++)
                    o[i][j] = fmaf(pr[i], vr[j], o[i][j]);
        }
    }

    // finalize
    float* Og = Out + ((size_t)b * TLEN + (size_t)qb * BM) * HD;
    const int h0 = tx * 4;
    #pragma unroll
    for (int i = 0; i < 4; i++) {
        float inv = 1.f / l[i];
        float4 ov = make_float4(o[i][0] * inv, o[i][1] * inv,
                                o[i][2] * inv, o[i][3] * inv);
        *(float4*)&Og[(size_t)(r0 + i) * HD + h0] = ov;
    }
}

// ---------------------------------------------------------------------------
extern "C" void kernel_launch(void* const* d_in, const int* in_sizes, int n_in,
                              void* d_out, int out_size)
{
    const float* x  = (const float*)d_in[0];
    const float* Wq = (const float*)d_in[1];
    const float* Wk = (const float*)d_in[2];
    const float* Wv = (const float*)d_in[3];
    float* out = (float*)d_out;

    const int smem_qkv  = (128 * TSTR + 128 * 192) * (int)sizeof(float); // 133120
    const int smem_attn = 4 * 64 * TSTR * (int)sizeof(float);            // 69632

    cudaFuncSetAttribute(qkv_kernel,
        cudaFuncAttributeMaxDynamicSharedMemorySize, smem_qkv);
    cudaFuncSetAttribute(attn_kernel,
        cudaFuncAttributeMaxDynamicSharedMemorySize, smem_attn);

    qkv_kernel<<<(NB * TLEN) / 64, 256, smem_qkv>>>(x, Wq, Wk, Wv);
    attn_kernel<<<dim3(TLEN / BM, NB), 256, smem_attn>>>(out);
}

// round 2
// speedup vs baseline: 2.5235x; 2.5235x over previous
#include <cuda_runtime.h>
#include <math.h>
#include <float.h>
#include <stdint.h>

#define NB    8
#define TLEN  4096
#define DM    128
#define HD    64
#define TSTR  68   // qkv kernel smem stride
#define SK    72   // attn smem stride (bank-conflict-free for mma fragment patterns)

// Scratch for Q/K/V projections (no allocation allowed in kernel_launch)
__device__ float g_Q[NB * TLEN * HD];
__device__ float g_K[NB * TLEN * HD];
__device__ float g_V[NB * TLEN * HD];

// ---------------------------------------------------------------------------
// helpers
// ---------------------------------------------------------------------------
__device__ __forceinline__ uint32_t f2tf32(float x) {
    uint32_t r;
    asm("cvt.rna.tf32.f32 %0, %1;" : "=r"(r) : "f"(x));
    return r;
}
__device__ __forceinline__ float ex2f(float x) {
    float r;
    asm("ex2.approx.ftz.f32 %0, %1;" : "=f"(r) : "f"(x));
    return r;
}
__device__ __forceinline__ void mma_tf32(float* d, const uint32_t* a,
                                         uint32_t b0, uint32_t b1) {
    asm volatile(
        "mma.sync.aligned.m16n8k8.row.col.f32.tf32.tf32.f32 "
        "{%0,%1,%2,%3}, {%4,%5,%6,%7}, {%8,%9}, {%0,%1,%2,%3};\n"
        : "+f"(d[0]), "+f"(d[1]), "+f"(d[2]), "+f"(d[3])
        : "r"(a[0]), "r"(a[1]), "r"(a[2]), "r"(a[3]), "r"(b0), "r"(b1));
}

// ---------------------------------------------------------------------------
// QKV projection (unchanged from R1): one block = 64 rows of x.
// ---------------------------------------------------------------------------
__global__ __launch_bounds__(256) void qkv_kernel(
    const float* __restrict__ x,
    const float* __restrict__ Wq,
    const float* __restrict__ Wk,
    const float* __restrict__ Wv)
{
    extern __shared__ float sm[];
    float* Xts = sm;              // [128][TSTR]
    float* Ws  = sm + 128 * TSTR; // [128][192]

    const int tid  = threadIdx.x;
    const int row0 = blockIdx.x * 64;

    const float* xg = x + (size_t)row0 * DM;
    #pragma unroll
    for (int idx = tid; idx < 64 * 128; idx += 256) {
        int r = idx >> 7;
        int k = idx & 127;
        Xts[k * TSTR + r] = xg[r * DM + k];
    }
    for (int idx = tid; idx < 128 * 192; idx += 256) {
        int k = idx / 192;
        int c = idx - k * 192;
        float w;
        if (c < 64)        w = Wq[k * 64 + c];
        else if (c < 128)  w = Wk[k * 64 + (c - 64)];
        else               w = Wv[k * 64 + (c - 128)];
        Ws[k * 192 + c] = w;
    }
    __syncthreads();

    const int ty = tid >> 4, tx = tid & 15;
    const int r0 = ty * 4;
    const int c0 = tx * 12;

    float acc[4][12];
    #pragma unroll
    for (int i = 0; i < 4; i++)
        #pragma unroll
        for (int j = 0; j < 12; j++) acc[i][j] = 0.f;

    #pragma unroll 8
    for (int k = 0; k < 128; k++) {
        float4 xv = *(const float4*)&Xts[k * TSTR + r0];
        float4 w0 = *(const float4*)&Ws[k * 192 + c0];
        float4 w1 = *(const float4*)&Ws[k * 192 + c0 + 4];
        float4 w2 = *(const float4*)&Ws[k * 192 + c0 + 8];
        float xr[4] = {xv.x, xv.y, xv.z, xv.w};
        float wr[12] = {w0.x, w0.y, w0.z, w0.w,
                        w1.x, w1.y, w1.z, w1.w,
                        w2.x, w2.y, w2.z, w2.w};
        #pragma unroll
        for (int i = 0; i < 4; i++)
            #pragma unroll
            for (int j = 0; j < 12; j++)
                acc[i][j] = fmaf(xr[i], wr[j], acc[i][j]);
    }

    #pragma unroll
    for (int i = 0; i < 4; i++) {
        int row = row0 + r0 + i;
        #pragma unroll
        for (int j = 0; j < 12; j++) {
            int c = c0 + j;
            float v = acc[i][j];
            if (c < 64)        g_Q[(size_t)row * HD + c]         = v;
            else if (c < 128)  g_K[(size_t)row * HD + (c - 64)]  = v;
            else               g_V[(size_t)row * HD + (c - 128)] = v;
        }
    }
}

// ---------------------------------------------------------------------------
// Causal flash attention on tensor cores (mma.sync m16n8k8 tf32).
// 128 threads = 4 warps; warp w owns q-rows [16w, 16w+16). BM=BN=64.
// Ks/Vs: [kv][hd] stride SK (conflict-free fragment loads).
// Pb:    [q][*]  stride SK; doubles as Q staging at start, P strip per kb.
// ---------------------------------------------------------------------------
__global__ __launch_bounds__(128) void attn_kernel(float* __restrict__ Out)
{
    extern __shared__ float sm[];
    float* Ks = sm;               // [64][SK]
    float* Vs = sm + 64 * SK;     // [64][SK]
    float* Pb = sm + 2 * 64 * SK; // [64][SK]

    const int qb   = (int)gridDim.x - 1 - (int)blockIdx.x; // longest first
    const int b    = blockIdx.y;
    const int tid  = threadIdx.x;
    const int warp = tid >> 5, lane = tid & 31;
    const int g    = lane >> 2;     // groupID (row within fragment)
    const int qi   = lane & 3;      // quad index (col within fragment)
    const int qrow = warp * 16 + g; // local q row for frag rows 0..7

    // --- stage Q tile into Pb (tf32-rounded), then pull A-fragments ---
    const float* Qg = g_Q + ((size_t)b * TLEN + (size_t)qb * 64) * HD;
    #pragma unroll
    for (int idx = tid; idx < 64 * 16; idx += 128) {
        int r = idx >> 4, c = (idx & 15) * 4;
        float4 v = *(const float4*)(Qg + r * HD + c);
        uint32_t* dst = (uint32_t*)&Pb[r * SK + c];
        dst[0] = f2tf32(v.x); dst[1] = f2tf32(v.y);
        dst[2] = f2tf32(v.z); dst[3] = f2tf32(v.w);
    }
    __syncthreads();

    uint32_t qa[8][4];
    #pragma unroll
    for (int ks = 0; ks < 8; ks++) {
        const uint32_t* P0 = (const uint32_t*)&Pb[qrow * SK + qi + 8 * ks];
        const uint32_t* P1 = (const uint32_t*)&Pb[(qrow + 8) * SK + qi + 8 * ks];
        qa[ks][0] = P0[0];
        qa[ks][1] = P1[0];
        qa[ks][2] = P0[4];
        qa[ks][3] = P1[4];
    }

    float o[8][4];
    #pragma unroll
    for (int n = 0; n < 8; n++)
        #pragma unroll
        for (int e = 0; e < 4; e++) o[n][e] = 0.f;
    float m0 = -1e30f, m1 = -1e30f, l0 = 0.f, l1 = 0.f;

    // 1/sqrt(128) * log2(e): softmax computed in exp2 domain
    const float SCL = 0.08838834764831845f * 1.4426950408889634f;

    for (int kb = 0; kb <= qb; kb++) {
        __syncthreads(); // everyone done with previous Ks/Vs/Pb

        const float* Kg = g_K + ((size_t)b * TLEN + (size_t)kb * 64) * HD;
        const float* Vg = g_V + ((size_t)b * TLEN + (size_t)kb * 64) * HD;
        #pragma unroll
        for (int idx = tid; idx < 64 * 16; idx += 128) {
            int r = idx >> 4, c = (idx & 15) * 4;
            float4 kv = *(const float4*)(Kg + r * HD + c);
            float4 vv = *(const float4*)(Vg + r * HD + c);
            uint32_t* kd = (uint32_t*)&Ks[r * SK + c];
            kd[0] = f2tf32(kv.x); kd[1] = f2tf32(kv.y);
            kd[2] = f2tf32(kv.z); kd[3] = f2tf32(kv.w);
            uint32_t* vd = (uint32_t*)&Vs[r * SK + c];
            vd[0] = f2tf32(vv.x); vd[1] = f2tf32(vv.y);
            vd[2] = f2tf32(vv.z); vd[3] = f2tf32(vv.w);
        }
        __syncthreads();

        // --- S = Q K^T : ks outer for ILP across 8 independent accumulators
        float s[8][4];
        #pragma unroll
        for (int n = 0; n < 8; n++)
            #pragma unroll
            for (int e = 0; e < 4; e++) s[n][e] = 0.f;

        #pragma unroll
        for (int ks = 0; ks < 8; ks++) {
            #pragma unroll
            for (int nt = 0; nt < 8; nt++) {
                uint32_t b0 = *(const uint32_t*)&Ks[(8 * nt + g) * SK + qi + 8 * ks];
                uint32_t b1 = *(const uint32_t*)&Ks[(8 * nt + g) * SK + qi + 4 + 8 * ks];
                mma_tf32(s[nt], qa[ks], b0, b1);
            }
        }

        // --- scale + causal mask (only on diagonal tile) ---
        const bool diag = (kb == qb);
        #pragma unroll
        for (int nt = 0; nt < 8; nt++) {
            int c0 = 8 * nt + 2 * qi;
            if (diag) {
                s[nt][0] = (c0     > qrow    ) ? -1e30f : s[nt][0] * SCL;
                s[nt][1] = (c0 + 1 > qrow    ) ? -1e30f : s[nt][1] * SCL;
                s[nt][2] = (c0     > qrow + 8) ? -1e30f : s[nt][2] * SCL;
                s[nt][3] = (c0 + 1 > qrow + 8) ? -1e30f : s[nt][3] * SCL;
            } else {
                s[nt][0] *= SCL; s[nt][1] *= SCL;
                s[nt][2] *= SCL; s[nt][3] *= SCL;
            }
        }

        // --- online softmax (exp2 domain), rows split between quad lanes ---
        float rm0 = -1e30f, rm1 = -1e30f;
        #pragma unroll
        for (int nt = 0; nt < 8; nt++) {
            rm0 = fmaxf(rm0, fmaxf(s[nt][0], s[nt][1]));
            rm1 = fmaxf(rm1, fmaxf(s[nt][2], s[nt][3]));
        }
        rm0 = fmaxf(rm0, __shfl_xor_sync(0xffffffffu, rm0, 1));
        rm0 = fmaxf(rm0, __shfl_xor_sync(0xffffffffu, rm0, 2));
        rm1 = fmaxf(rm1, __shfl_xor_sync(0xffffffffu, rm1, 1));
        rm1 = fmaxf(rm1, __shfl_xor_sync(0xffffffffu, rm1, 2));

        float m0n = fmaxf(m0, rm0), m1n = fmaxf(m1, rm1);
        float a0 = ex2f(m0 - m0n), a1 = ex2f(m1 - m1n);
        m0 = m0n; m1 = m1n;

        float rs0 = 0.f, rs1 = 0.f;
        #pragma unroll
        for (int nt = 0; nt < 8; nt++) {
            s[nt][0] = ex2f(s[nt][0] - m0n);
            s[nt][1] = ex2f(s[nt][1] - m0n);
            s[nt][2] = ex2f(s[nt][2] - m1n);
            s[nt][3] = ex2f(s[nt][3] - m1n);
            rs0 += s[nt][0] + s[nt][1];
            rs1 += s[nt][2] + s[nt][3];
        }
        rs0 += __shfl_xor_sync(0xffffffffu, rs0, 1);
        rs0 += __shfl_xor_sync(0xffffffffu, rs0, 2);
        rs1 += __shfl_xor_sync(0xffffffffu, rs1, 1);
        rs1 += __shfl_xor_sync(0xffffffffu, rs1, 2);
        l0 = l0 * a0 + rs0;
        l1 = l1 * a1 + rs1;

        #pragma unroll
        for (int nt = 0; nt < 8; nt++) {
            o[nt][0] *= a0; o[nt][1] *= a0;
            o[nt][2] *= a1; o[nt][3] *= a1;
        }

        // --- store P strip (tf32) into per-warp region of Pb ---
        #pragma unroll
        for (int nt = 0; nt < 8; nt++) {
            uint2 p01 = make_uint2(f2tf32(s[nt][0]), f2tf32(s[nt][1]));
            *(uint2*)&Pb[qrow * SK + 8 * nt + 2 * qi] = p01;
            uint2 p23 = make_uint2(f2tf32(s[nt][2]), f2tf32(s[nt][3]));
            *(uint2*)&Pb[(qrow + 8) * SK + 8 * nt + 2 * qi] = p23;
        }
        __syncwarp();

        // --- O += P V ---
        #pragma unroll
        for (int ks = 0; ks < 8; ks++) {
            uint32_t pa[4];
            const uint32_t* P0 = (const uint32_t*)&Pb[qrow * SK + qi + 8 * ks];
            const uint32_t* P1 = (const uint32_t*)&Pb[(qrow + 8) * SK + qi + 8 * ks];
            pa[0] = P0[0]; pa[1] = P1[0]; pa[2] = P0[4]; pa[3] = P1[4];
            #pragma unroll
            for (int nt = 0; nt < 8; nt++) {
                uint32_t b0 = *(const uint32_t*)&Vs[(qi + 8 * ks) * SK + 8 * nt + g];
                uint32_t b1 = *(const uint32_t*)&Vs[(qi + 4 + 8 * ks) * SK + 8 * nt + g];
                mma_tf32(o[nt], pa, b0, b1);
            }
        }
    }

    // --- finalize: divide by l, write out ---
    float i0 = 1.f / l0, i1 = 1.f / l1;
    float* Og = Out + ((size_t)b * TLEN + (size_t)qb * 64) * HD;
    #pragma unroll
    for (int nt = 0; nt < 8; nt++) {
        float2 v0 = make_float2(o[nt][0] * i0, o[nt][1] * i0);
        *(float2*)&Og[(size_t)qrow * HD + 8 * nt + 2 * qi] = v0;
        float2 v1 = make_float2(o[nt][2] * i1, o[nt][3] * i1);
        *(float2*)&Og[(size_t)(qrow + 8) * HD + 8 * nt + 2 * qi] = v1;
    }
}

// ---------------------------------------------------------------------------
extern "C" void kernel_launch(void* const* d_in, const int* in_sizes, int n_in,
                              void* d_out, int out_size)
{
    const float* x  = (const float*)d_in[0];
    const float* Wq = (const float*)d_in[1];
    const float* Wk = (const float*)d_in[2];
    const float* Wv = (const float*)d_in[3];
    float* out = (float*)d_out;

    const int smem_qkv  = (128 * TSTR + 128 * 192) * (int)sizeof(float); // 133120
    const int smem_attn = 3 * 64 * SK * (int)sizeof(float);              // 55296

    cudaFuncSetAttribute(qkv_kernel,
        cudaFuncAttributeMaxDynamicSharedMemorySize, smem_qkv);
    cudaFuncSetAttribute(attn_kernel,
        cudaFuncAttributeMaxDynamicSharedMemorySize, smem_attn);

    qkv_kernel<<<(NB * TLEN) / 64, 256, smem_qkv>>>(x, Wq, Wk, Wv);
    attn_kernel<<<dim3(TLEN / 64, NB), 128, smem_attn>>>(out);
}

// round 3
// speedup vs baseline: 2.9201x; 1.1572x over previous
#include <cuda_runtime.h>
#include <math.h>
#include <float.h>
#include <stdint.h>

#define NB    8
#define TLEN  4096
#define BT    (NB * TLEN)   // 32768
#define DM    128
#define HD    64
#define SK    68            // attn smem stride (f32), 16B-aligned rows, ldmatrix conflict-free

// Scratch (tf32-rounded bit patterns stored as float)
__device__ float g_Q[BT * HD];
__device__ float g_K[BT * HD];
__device__ float g_Vt[HD * BT];   // V transposed: [hd][b*T + t]

// ---------------------------------------------------------------------------
// helpers
// ---------------------------------------------------------------------------
__device__ __forceinline__ uint32_t f2tf32(float x) {
    uint32_t r;
    asm("cvt.rna.tf32.f32 %0, %1;" : "=r"(r) : "f"(x));
    return r;
}
__device__ __forceinline__ float tf32f(float x) {
    return __uint_as_float(f2tf32(x));
}
__device__ __forceinline__ float ex2f(float x) {
    float r;
    asm("ex2.approx.ftz.f32 %0, %1;" : "=f"(r) : "f"(x));
    return r;
}
__device__ __forceinline__ void mma_tf32(float* d, const uint32_t* a,
                                         uint32_t b0, uint32_t b1) {
    asm volatile(
        "mma.sync.aligned.m16n8k8.row.col.f32.tf32.tf32.f32 "
        "{%0,%1,%2,%3}, {%4,%5,%6,%7}, {%8,%9}, {%0,%1,%2,%3};\n"
        : "+f"(d[0]), "+f"(d[1]), "+f"(d[2]), "+f"(d[3])
        : "r"(a[0]), "r"(a[1]), "r"(a[2]), "r"(a[3]), "r"(b0), "r"(b1));
}
__device__ __forceinline__ void ldm_x4(uint32_t* r, const float* p) {
    uint32_t a = (uint32_t)__cvta_generic_to_shared(p);
    asm volatile("ldmatrix.sync.aligned.m8n8.x4.shared.b16 {%0,%1,%2,%3}, [%4];"
        : "=r"(r[0]), "=r"(r[1]), "=r"(r[2]), "=r"(r[3]) : "r"(a));
}

// ---------------------------------------------------------------------------
// QKV projection on tensor cores. CTA = 64 x-rows; out 64x192, K=128.
// 128 threads = 4 warps: warp (wr=w>>1, wc=w&1) -> rows 32*wr..+31, cols 96*wc..+95.
// Xs [64][132] (tf32-rounded), Ws [128][196] natural k-major (scalar B loads,
// bank = 4*qi + g  -> conflict-free).
// Outputs tf32-rounded: g_Q/g_K natural, V transposed into g_Vt.
// ---------------------------------------------------------------------------
__global__ __launch_bounds__(128) void qkv_kernel(
    const float* __restrict__ x,
    const float* __restrict__ Wq,
    const float* __restrict__ Wk,
    const float* __restrict__ Wv)
{
    extern __shared__ float sm[];
    float* Xs = sm;              // [64][132]
    float* Ws = sm + 64 * 132;   // [128][196]

    const int tid  = threadIdx.x;
    const int row0 = blockIdx.x * 64;

    // stage X (tf32-rounded)
    #pragma unroll
    for (int idx = tid; idx < 64 * 32; idx += 128) {
        int r = idx >> 5, c4 = idx & 31;
        float4 v = *(const float4*)(x + (size_t)(row0 + r) * DM + 4 * c4);
        v.x = tf32f(v.x); v.y = tf32f(v.y); v.z = tf32f(v.z); v.w = tf32f(v.w);
        *(float4*)&Xs[r * 132 + 4 * c4] = v;
    }
    // stage fused W [128][196] (tf32-rounded)
    for (int idx = tid; idx < 128 * 48; idx += 128) {
        int k = idx / 48, c4 = idx % 48;
        const float* src = (c4 < 16) ? (Wq + k * 64 + 4 * c4)
                         : (c4 < 32) ? (Wk + k * 64 + 4 * (c4 - 16))
                                     : (Wv + k * 64 + 4 * (c4 - 32));
        float4 v = *(const float4*)src;
        v.x = tf32f(v.x); v.y = tf32f(v.y); v.z = tf32f(v.z); v.w = tf32f(v.w);
        *(float4*)&Ws[k * 196 + 4 * c4] = v;
    }
    __syncthreads();

    const int warp = tid >> 5, lane = tid & 31;
    const int g = lane >> 2, qi = lane & 3;
    const int rowbase = 32 * (warp >> 1);
    const int colbase = 96 * (warp & 1);
    const int arow = ((lane >> 3) & 1) * 8 + (lane & 7);
    const int acol = (lane >> 4) * 4;

    float s[2][12][4];
    #pragma unroll
    for (int rg = 0; rg < 2; rg++)
        #pragma unroll
        for (int nt = 0; nt < 12; nt++)
            #pragma unroll
            for (int e = 0; e < 4; e++) s[rg][nt][e] = 0.f;

    #pragma unroll
    for (int ks = 0; ks < 16; ks++) {
        uint32_t qa0[4], qa1[4];
        ldm_x4(qa0, &Xs[(rowbase + arow) * 132 + 8 * ks + acol]);
        ldm_x4(qa1, &Xs[(rowbase + 16 + arow) * 132 + 8 * ks + acol]);
        #pragma unroll
        for (int nt = 0; nt < 12; nt++) {
            uint32_t b0 = __float_as_uint(Ws[(8 * ks + qi) * 196 + colbase + 8 * nt + g]);
            uint32_t b1 = __float_as_uint(Ws[(8 * ks + qi + 4) * 196 + colbase + 8 * nt + g]);
            mma_tf32(s[0][nt], qa0, b0, b1);
            mma_tf32(s[1][nt], qa1, b0, b1);
        }
    }

    // scatter outputs (tf32-rounded)
    #pragma unroll
    for (int rg = 0; rg < 2; rg++) {
        #pragma unroll
        for (int nt = 0; nt < 12; nt++) {
            int c0 = colbase + 8 * nt + 2 * qi;
            int rA = row0 + rowbase + 16 * rg + g;
            int rB = rA + 8;
            #pragma unroll
            for (int half = 0; half < 2; half++) {
                int r = half ? rB : rA;
                float v0 = tf32f(s[rg][nt][2 * half + 0]);
                float v1 = tf32f(s[rg][nt][2 * half + 1]);
                if (c0 < 64) {
                    *(float2*)&g_Q[(size_t)r * HD + c0] = make_float2(v0, v1);
                } else if (c0 < 128) {
                    *(float2*)&g_K[(size_t)r * HD + (c0 - 64)] = make_float2(v0, v1);
                } else {
                    int h = c0 - 128;
                    g_Vt[(size_t)h * BT + r]       = v0;
                    g_Vt[(size_t)(h + 1) * BT + r] = v1;
                }
            }
        }
    }
}

// ---------------------------------------------------------------------------
// Causal flash attention, tensor cores + ldmatrix. 64 threads = 2 warps.
// Warp w owns q-rows [32w, 32w+32) (two 16-row fragments). BM=BN=64.
// Ks: [kv][SK] natural; Vt: [hd][SK]; Pb: [q][SK] (Q staging + P strip).
// ---------------------------------------------------------------------------
__global__ __launch_bounds__(64, 4) void attn_kernel(float* __restrict__ Out)
{
    extern __shared__ float sm[];
    float* Ks = sm;               // [64][SK]
    float* Vt = sm + 64 * SK;     // [64][SK]  (rows = hd)
    float* Pb = sm + 2 * 64 * SK; // [64][SK]

    const int qb   = 63 - (int)blockIdx.x;  // longest first
    const int b    = blockIdx.y;
    const int tid  = threadIdx.x;
    const int warp = tid >> 5, lane = tid & 31;
    const int g    = lane >> 2, qi = lane & 3;

    // ldmatrix lane->address patterns
    const int arow = ((lane >> 3) & 1) * 8 + (lane & 7);  // A-frag rows
    const int acol = (lane >> 4) * 4;
    const int brow = (lane & 7) + ((lane >> 4) << 3);     // B-frag rows (within 16)
    const int bcol = ((lane >> 3) & 1) * 4;

    // --- stage this warp's Q rows into Pb (already tf32), pull A-frags ---
    const float* Qg = g_Q + ((size_t)b * TLEN + (size_t)qb * 64 + 32 * warp) * HD;
    #pragma unroll
    for (int idx = lane; idx < 32 * 16; idx += 32) {
        int r = idx >> 4, c4 = idx & 15;
        *(float4*)&Pb[(32 * warp + r) * SK + 4 * c4] =
            *(const float4*)(Qg + (size_t)r * HD + 4 * c4);
    }
    __syncwarp();

    uint32_t qa[2][8][4];
    #pragma unroll
    for (int rg = 0; rg < 2; rg++)
        #pragma unroll
        for (int ks = 0; ks < 8; ks++)
            ldm_x4(qa[rg][ks], &Pb[(32 * warp + 16 * rg + arow) * SK + 8 * ks + acol]);

    float o[2][8][4];
    #pragma unroll
    for (int rg = 0; rg < 2; rg++)
        #pragma unroll
        for (int nt = 0; nt < 8; nt++)
            #pragma unroll
            for (int e = 0; e < 4; e++) o[rg][nt][e] = 0.f;
    float m[4] = {-1e30f, -1e30f, -1e30f, -1e30f};
    float l[4] = {0.f, 0.f, 0.f, 0.f};

    // 1/sqrt(128) * log2(e): softmax in exp2 domain
    const float SCL = 0.08838834764831845f * 1.4426950408889634f;

    for (int kb = 0; kb <= qb; kb++) {
        __syncthreads();  // previous Ks/Vt readers done

        const float* Kg = g_K + ((size_t)b * TLEN + (size_t)kb * 64) * HD;
        const float* Vg = g_Vt + (size_t)b * TLEN + (size_t)kb * 64;
        #pragma unroll
        for (int idx = tid; idx < 64 * 16; idx += 64) {
            int r = idx >> 4, c4 = idx & 15;
            *(float4*)&Ks[r * SK + 4 * c4] = *(const float4*)(Kg + (size_t)r * HD + 4 * c4);
            *(float4*)&Vt[r * SK + 4 * c4] = *(const float4*)(Vg + (size_t)r * BT + 4 * c4);
        }
        __syncthreads();

        // --- S = Q K^T ---
        float s[2][8][4];
        #pragma unroll
        for (int rg = 0; rg < 2; rg++)
            #pragma unroll
            for (int nt = 0; nt < 8; nt++)
                #pragma unroll
                for (int e = 0; e < 4; e++) s[rg][nt][e] = 0.f;

        #pragma unroll
        for (int ks = 0; ks < 8; ks++) {
            #pragma unroll
            for (int ntp = 0; ntp < 4; ntp++) {
                uint32_t kf[4];
                ldm_x4(kf, &Ks[(16 * ntp + brow) * SK + 8 * ks + bcol]);
                mma_tf32(s[0][2 * ntp],     qa[0][ks], kf[0], kf[1]);
                mma_tf32(s[1][2 * ntp],     qa[1][ks], kf[0], kf[1]);
                mma_tf32(s[0][2 * ntp + 1], qa[0][ks], kf[2], kf[3]);
                mma_tf32(s[1][2 * ntp + 1], qa[1][ks], kf[2], kf[3]);
            }
        }

        // --- scale + causal mask ---
        const bool diag = (kb == qb);
        #pragma unroll
        for (int rg = 0; rg < 2; rg++) {
            int qr = 32 * warp + 16 * rg + g;
            #pragma unroll
            for (int nt = 0; nt < 8; nt++) {
                int c0 = 8 * nt + 2 * qi;
                if (diag) {
                    s[rg][nt][0] = (c0     > qr    ) ? -1e30f : s[rg][nt][0] * SCL;
                    s[rg][nt][1] = (c0 + 1 > qr    ) ? -1e30f : s[rg][nt][1] * SCL;
                    s[rg][nt][2] = (c0     > qr + 8) ? -1e30f : s[rg][nt][2] * SCL;
                    s[rg][nt][3] = (c0 + 1 > qr + 8) ? -1e30f : s[rg][nt][3] * SCL;
                } else {
                    s[rg][nt][0] *= SCL; s[rg][nt][1] *= SCL;
                    s[rg][nt][2] *= SCL; s[rg][nt][3] *= SCL;
                }
            }
        }

        // --- online softmax (exp2 domain) ---
        #pragma unroll
        for (int rg = 0; rg < 2; rg++) {
            float rm0 = -1e30f, rm1 = -1e30f;
            #pragma unroll
            for (int nt = 0; nt < 8; nt++) {
                rm0 = fmaxf(rm0, fmaxf(s[rg][nt][0], s[rg][nt][1]));
                rm1 = fmaxf(rm1, fmaxf(s[rg][nt][2], s[rg][nt][3]));
            }
            rm0 = fmaxf(rm0, __shfl_xor_sync(0xffffffffu, rm0, 1));
            rm0 = fmaxf(rm0, __shfl_xor_sync(0xffffffffu, rm0, 2));
            rm1 = fmaxf(rm1, __shfl_xor_sync(0xffffffffu, rm1, 1));
            rm1 = fmaxf(rm1, __shfl_xor_sync(0xffffffffu, rm1, 2));

            float mn0 = fmaxf(m[2 * rg],     rm0);
            float mn1 = fmaxf(m[2 * rg + 1], rm1);
            float a0 = ex2f(m[2 * rg]     - mn0);
            float a1 = ex2f(m[2 * rg + 1] - mn1);
            m[2 * rg] = mn0; m[2 * rg + 1] = mn1;

            float rs0 = 0.f, rs1 = 0.f;
            #pragma unroll
            for (int nt = 0; nt < 8; nt++) {
                s[rg][nt][0] = ex2f(s[rg][nt][0] - mn0);
                s[rg][nt][1] = ex2f(s[rg][nt][1] - mn0);
                s[rg][nt][2] = ex2f(s[rg][nt][2] - mn1);
                s[rg][nt][3] = ex2f(s[rg][nt][3] - mn1);
                rs0 += s[rg][nt][0] + s[rg][nt][1];
                rs1 += s[rg][nt][2] + s[rg][nt][3];
            }
            rs0 += __shfl_xor_sync(0xffffffffu, rs0, 1);
            rs0 += __shfl_xor_sync(0xffffffffu, rs0, 2);
            rs1 += __shfl_xor_sync(0xffffffffu, rs1, 1);
            rs1 += __shfl_xor_sync(0xffffffffu, rs1, 2);
            l[2 * rg]     = l[2 * rg]     * a0 + rs0;
            l[2 * rg + 1] = l[2 * rg + 1] * a1 + rs1;

            #pragma unroll
            for (int nt = 0; nt < 8; nt++) {
                o[rg][nt][0] *= a0; o[rg][nt][1] *= a0;
                o[rg][nt][2] *= a1; o[rg][nt][3] *= a1;
            }

            // store P strip (tf32) into this warp's Pb rows
            int pr = 32 * warp + 16 * rg + g;
            #pragma unroll
            for (int nt = 0; nt < 8; nt++) {
                *(uint2*)&Pb[pr * SK + 8 * nt + 2 * qi] =
                    make_uint2(f2tf32(s[rg][nt][0]), f2tf32(s[rg][nt][1]));
                *(uint2*)&Pb[(pr + 8) * SK + 8 * nt + 2 * qi] =
                    make_uint2(f2tf32(s[rg][nt][2]), f2tf32(s[rg][nt][3]));
            }
        }
        __syncwarp();

        // --- O += P V ---
        #pragma unroll
        for (int ks = 0; ks < 8; ks++) {
            uint32_t pa0[4], pa1[4];
            ldm_x4(pa0, &Pb[(32 * warp + arow) * SK + 8 * ks + acol]);
            ldm_x4(pa1, &Pb[(32 * warp + 16 + arow) * SK + 8 * ks + acol]);
            #pragma unroll
            for (int ntp = 0; ntp < 4; ntp++) {
                uint32_t vf[4];
                ldm_x4(vf, &Vt[(16 * ntp + brow) * SK + 8 * ks + bcol]);
                mma_tf32(o[0][2 * ntp],     pa0, vf[0], vf[1]);
                mma_tf32(o[1][2 * ntp],     pa1, vf[0], vf[1]);
                mma_tf32(o[0][2 * ntp + 1], pa0, vf[2], vf[3]);
                mma_tf32(o[1][2 * ntp + 1], pa1, vf[2], vf[3]);
            }
        }
    }

    // --- finalize ---
    float* Og = Out + ((size_t)b * TLEN + (size_t)qb * 64) * HD;
    #pragma unroll
    for (int rg = 0; rg < 2; rg++) {
        float i0 = 1.f / l[2 * rg], i1 = 1.f / l[2 * rg + 1];
        int r = 32 * warp + 16 * rg + g;
        #pragma unroll
        for (int nt = 0; nt < 8; nt++) {
            int c0 = 8 * nt + 2 * qi;
            *(float2*)&Og[(size_t)r * HD + c0] =
                make_float2(o[rg][nt][0] * i0, o[rg][nt][1] * i0);
            *(float2*)&Og[(size_t)(r + 8) * HD + c0] =
                make_float2(o[rg][nt][2] * i1, o[rg][nt][3] * i1);
        }
    }
}

// ---------------------------------------------------------------------------
extern "C" void kernel_launch(void* const* d_in, const int* in_sizes, int n_in,
                              void* d_out, int out_size)
{
    const float* x  = (const float*)d_in[0];
    const float* Wq = (const float*)d_in[1];
    const float* Wk = (const float*)d_in[2];
    const float* Wv = (const float*)d_in[3];
    float* out = (float*)d_out;

    const int smem_qkv  = (64 * 132 + 128 * 196) * (int)sizeof(float); // 134144
    const int smem_attn = 3 * 64 * SK * (int)sizeof(float);            // 52224

    cudaFuncSetAttribute(qkv_kernel,
        cudaFuncAttributeMaxDynamicSharedMemorySize, smem_qkv);
    cudaFuncSetAttribute(attn_kernel,
        cudaFuncAttributeMaxDynamicSharedMemorySize, smem_attn);

    qkv_kernel<<<BT / 64, 128, smem_qkv>>>(x, Wq, Wk, Wv);
    attn_kernel<<<dim3(TLEN / 64, NB), 64, smem_attn>>>(out);
}

// round 4
// speedup vs baseline: 3.1623x; 1.0830x over previous
#include <cuda_runtime.h>
#include <math.h>
#include <float.h>
#include <stdint.h>

#define NB    8
#define TLEN  4096
#define BT    (NB * TLEN)   // 32768
#define DM    128
#define HD    64
#define SK    68            // attn smem stride (f32)

// Scratch (tf32-rounded bit patterns stored as float)
__device__ float g_Q[BT * HD];
__device__ float g_K[BT * HD];
__device__ float g_Vt[HD * BT];   // V transposed: [hd][b*T + t]

// ---------------------------------------------------------------------------
// helpers
// ---------------------------------------------------------------------------
__device__ __forceinline__ uint32_t f2tf32(float x) {
    uint32_t r;
    asm("cvt.rna.tf32.f32 %0, %1;" : "=r"(r) : "f"(x));
    return r;
}
__device__ __forceinline__ float tf32f(float x) {
    return __uint_as_float(f2tf32(x));
}
__device__ __forceinline__ float ex2f(float x) {
    float r;
    asm("ex2.approx.ftz.f32 %0, %1;" : "=f"(r) : "f"(x));
    return r;
}
__device__ __forceinline__ void mma_tf32(float* d, const uint32_t* a,
                                         uint32_t b0, uint32_t b1) {
    asm volatile(
        "mma.sync.aligned.m16n8k8.row.col.f32.tf32.tf32.f32 "
        "{%0,%1,%2,%3}, {%4,%5,%6,%7}, {%8,%9}, {%0,%1,%2,%3};\n"
        : "+f"(d[0]), "+f"(d[1]), "+f"(d[2]), "+f"(d[3])
        : "r"(a[0]), "r"(a[1]), "r"(a[2]), "r"(a[3]), "r"(b0), "r"(b1));
}
__device__ __forceinline__ void ldm_x4(uint32_t* r, const float* p) {
    uint32_t a = (uint32_t)__cvta_generic_to_shared(p);
    asm volatile("ldmatrix.sync.aligned.m8n8.x4.shared.b16 {%0,%1,%2,%3}, [%4];"
        : "=r"(r[0]), "=r"(r[1]), "=r"(r[2]), "=r"(r[3]) : "r"(a));
}
__device__ __forceinline__ void cpa16(float* dst, const float* src) {
    uint32_t d = (uint32_t)__cvta_generic_to_shared(dst);
    asm volatile("cp.async.cg.shared.global [%0], [%1], 16;" :: "r"(d), "l"(src));
}
#define CP_COMMIT() asm volatile("cp.async.commit_group;")
#define CP_WAIT0()  asm volatile("cp.async.wait_group 0;" ::: "memory")

// ---------------------------------------------------------------------------
// QKV projection on tensor cores. CTA = 64 x-rows, 128 thr = 4 warps.
// warp (rh=w>>1, ch=w&1): rows 32*rh..+31, cols 96*ch..+95.
// Xs [64][132] tf32-rounded in smem; W B-fragments read straight from global
// (W is 96KB total -> L1-resident after warmup) with cvt in registers.
// ---------------------------------------------------------------------------
__global__ __launch_bounds__(128) void qkv_kernel(
    const float* __restrict__ x,
    const float* __restrict__ Wq,
    const float* __restrict__ Wk,
    const float* __restrict__ Wv)
{
    extern __shared__ float sm[];
    float* Xs = sm;              // [64][132]

    const int tid  = threadIdx.x;
    const int row0 = blockIdx.x * 64;

    #pragma unroll
    for (int idx = tid; idx < 64 * 32; idx += 128) {
        int r = idx >> 5, c4 = idx & 31;
        float4 v = *(const float4*)(x + (size_t)(row0 + r) * DM + 4 * c4);
        v.x = tf32f(v.x); v.y = tf32f(v.y); v.z = tf32f(v.z); v.w = tf32f(v.w);
        *(float4*)&Xs[r * 132 + 4 * c4] = v;
    }
    __syncthreads();

    const int warp = tid >> 5, lane = tid & 31;
    const int g = lane >> 2, qi = lane & 3;
    const int rowbase = 32 * (warp >> 1);
    const int colbase = 96 * (warp & 1);
    const int arow = ((lane >> 3) & 1) * 8 + (lane & 7);
    const int acol = (lane >> 4) * 4;

    // per-nt W column pointers (uniform within each 8-col group)
    const float* wp[12];
    #pragma unroll
    for (int nt = 0; nt < 12; nt++) {
        int c = colbase + 8 * nt + g;
        const float* Wb = (c < 64) ? Wq : ((c < 128) ? Wk : Wv);
        wp[nt] = Wb + (c & 63);
    }

    float s[2][12][4];
    #pragma unroll
    for (int rg = 0; rg < 2; rg++)
        #pragma unroll
        for (int nt = 0; nt < 12; nt++)
            #pragma unroll
            for (int e = 0; e < 4; e++) s[rg][nt][e] = 0.f;

    #pragma unroll
    for (int ks = 0; ks < 16; ks++) {
        uint32_t qa0[4], qa1[4];
        ldm_x4(qa0, &Xs[(rowbase + arow) * 132 + 8 * ks + acol]);
        ldm_x4(qa1, &Xs[(rowbase + 16 + arow) * 132 + 8 * ks + acol]);
        int k0 = (8 * ks + qi) * 64, k1 = (8 * ks + qi + 4) * 64;
        #pragma unroll
        for (int nt = 0; nt < 12; nt++) {
            uint32_t b0 = f2tf32(__ldg(wp[nt] + k0));
            uint32_t b1 = f2tf32(__ldg(wp[nt] + k1));
            mma_tf32(s[0][nt], qa0, b0, b1);
            mma_tf32(s[1][nt], qa1, b0, b1);
        }
    }

    // scatter outputs (tf32-rounded): Q/K natural, V transposed
    #pragma unroll
    for (int rg = 0; rg < 2; rg++) {
        #pragma unroll
        for (int nt = 0; nt < 12; nt++) {
            int c0 = colbase + 8 * nt + 2 * qi;
            int rA = row0 + rowbase + 16 * rg + g;
            #pragma unroll
            for (int half = 0; half < 2; half++) {
                int r = rA + 8 * half;
                float v0 = tf32f(s[rg][nt][2 * half + 0]);
                float v1 = tf32f(s[rg][nt][2 * half + 1]);
                if (c0 < 64) {
                    *(float2*)&g_Q[(size_t)r * HD + c0] = make_float2(v0, v1);
                } else if (c0 < 128) {
                    *(float2*)&g_K[(size_t)r * HD + (c0 - 64)] = make_float2(v0, v1);
                } else {
                    int h = c0 - 128;
                    g_Vt[(size_t)h * BT + r]       = v0;
                    g_Vt[(size_t)(h + 1) * BT + r] = v1;
                }
            }
        }
    }
}

// ---------------------------------------------------------------------------
// Causal flash attention, tensor cores + ldmatrix + cp.async double buffering.
// 64 threads = 2 warps; warp w owns q-rows [32w, 32w+32). BM=BN=64.
// smem: K[2] and V[2] tiles, [64][SK] each. P fragments built by register
// shuffle from the S accumulators (no smem round trip).
// ---------------------------------------------------------------------------
__global__ __launch_bounds__(64, 3) void attn_kernel(float* __restrict__ Out)
{
    extern __shared__ float sm[];
    float* Kb[2] = { sm,               sm + 64 * SK };
    float* Vb[2] = { sm + 2 * 64 * SK, sm + 3 * 64 * SK };

    const int qb   = 63 - (int)blockIdx.x;  // longest first
    const int b    = blockIdx.y;
    const int tid  = threadIdx.x;
    const int warp = tid >> 5, lane = tid & 31;
    const int g    = lane >> 2, qi = lane & 3;

    const int arow = ((lane >> 3) & 1) * 8 + (lane & 7);
    const int acol = (lane >> 4) * 4;
    const int brow = (lane & 7) + ((lane >> 4) << 3);
    const int bcol = ((lane >> 3) & 1) * 4;

    const float* Kg0 = g_K + (size_t)b * TLEN * HD;
    const float* Vg0 = g_Vt + (size_t)b * TLEN;

    // prefetch tile 0 (group 0)
    #pragma unroll
    for (int idx = tid; idx < 64 * 16; idx += 64) {
        int r = idx >> 4, c4 = (idx & 15) * 4;
        cpa16(&Kb[0][r * SK + c4], Kg0 + (size_t)r * HD + c4);
        cpa16(&Vb[0][r * SK + c4], Vg0 + (size_t)r * BT + c4);
    }
    CP_COMMIT();

    // stage Q (already tf32) into Vb[1], pull A-fragments
    const float* Qg = g_Q + ((size_t)b * TLEN + (size_t)qb * 64) * HD;
    #pragma unroll
    for (int idx = tid; idx < 64 * 16; idx += 64) {
        int r = idx >> 4, c4 = (idx & 15) * 4;
        *(float4*)&Vb[1][r * SK + c4] = *(const float4*)(Qg + (size_t)r * HD + c4);
    }
    __syncthreads();

    uint32_t qa[2][8][4];
    #pragma unroll
    for (int rg = 0; rg < 2; rg++)
        #pragma unroll
        for (int ks = 0; ks < 8; ks++)
            ldm_x4(qa[rg][ks], &Vb[1][(32 * warp + 16 * rg + arow) * SK + 8 * ks + acol]);

    float o[2][8][4];
    #pragma unroll
    for (int rg = 0; rg < 2; rg++)
        #pragma unroll
        for (int nt = 0; nt < 8; nt++)
            #pragma unroll
            for (int e = 0; e < 4; e++) o[rg][nt][e] = 0.f;
    float m[4] = {-1e30f, -1e30f, -1e30f, -1e30f};
    float l[4] = {0.f, 0.f, 0.f, 0.f};

    const float SCL = 0.08838834764831845f * 1.4426950408889634f;
    const int srcA = (lane & ~3) | (qi >> 1);        // shuffle src for cols qi
    const int srcB = srcA + 2;                        // shuffle src for cols qi+4
    const bool oddq = (qi & 1);

    for (int kb = 0; kb <= qb; kb++) {
        const int cur = kb & 1;

        CP_WAIT0();          // tile kb landed
        __syncthreads();     // visible to all; everyone done with buf[1-cur]

        // prefetch tile kb+1 into the other buffers
        if (kb < qb) {
            const float* Kg = Kg0 + (size_t)(kb + 1) * 64 * HD;
            const float* Vg = Vg0 + (size_t)(kb + 1) * 64;
            #pragma unroll
            for (int idx = tid; idx < 64 * 16; idx += 64) {
                int r = idx >> 4, c4 = (idx & 15) * 4;
                cpa16(&Kb[1 - cur][r * SK + c4], Kg + (size_t)r * HD + c4);
                cpa16(&Vb[1 - cur][r * SK + c4], Vg + (size_t)r * BT + c4);
            }
        }
        CP_COMMIT();

        // --- S = Q K^T ---
        float s[2][8][4];
        #pragma unroll
        for (int rg = 0; rg < 2; rg++)
            #pragma unroll
            for (int nt = 0; nt < 8; nt++)
                #pragma unroll
                for (int e = 0; e < 4; e++) s[rg][nt][e] = 0.f;

        #pragma unroll
        for (int ks = 0; ks < 8; ks++) {
            #pragma unroll
            for (int ntp = 0; ntp < 4; ntp++) {
                uint32_t kf[4];
                ldm_x4(kf, &Kb[cur][(16 * ntp + brow) * SK + 8 * ks + bcol]);
                mma_tf32(s[0][2 * ntp],     qa[0][ks], kf[0], kf[1]);
                mma_tf32(s[1][2 * ntp],     qa[1][ks], kf[0], kf[1]);
                mma_tf32(s[0][2 * ntp + 1], qa[0][ks], kf[2], kf[3]);
                mma_tf32(s[1][2 * ntp + 1], qa[1][ks], kf[2], kf[3]);
            }
        }

        // --- scale + causal mask ---
        const bool diag = (kb == qb);
        #pragma unroll
        for (int rg = 0; rg < 2; rg++) {
            int qr = 32 * warp + 16 * rg + g;
            #pragma unroll
            for (int nt = 0; nt < 8; nt++) {
                int c0 = 8 * nt + 2 * qi;
                if (diag) {
                    s[rg][nt][0] = (c0     > qr    ) ? -1e30f : s[rg][nt][0] * SCL;
                    s[rg][nt][1] = (c0 + 1 > qr    ) ? -1e30f : s[rg][nt][1] * SCL;
                    s[rg][nt][2] = (c0     > qr + 8) ? -1e30f : s[rg][nt][2] * SCL;
                    s[rg][nt][3] = (c0 + 1 > qr + 8) ? -1e30f : s[rg][nt][3] * SCL;
                } else {
                    s[rg][nt][0] *= SCL; s[rg][nt][1] *= SCL;
                    s[rg][nt][2] *= SCL; s[rg][nt][3] *= SCL;
                }
            }
        }

        // --- online softmax (exp2 domain); P rounded to tf32 in-register ---
        #pragma unroll
        for (int rg = 0; rg < 2; rg++) {
            float rm0 = -1e30f, rm1 = -1e30f;
            #pragma unroll
            for (int nt = 0; nt < 8; nt++) {
                rm0 = fmaxf(rm0, fmaxf(s[rg][nt][0], s[rg][nt][1]));
                rm1 = fmaxf(rm1, fmaxf(s[rg][nt][2], s[rg][nt][3]));
            }
            rm0 = fmaxf(rm0, __shfl_xor_sync(0xffffffffu, rm0, 1));
            rm0 = fmaxf(rm0, __shfl_xor_sync(0xffffffffu, rm0, 2));
            rm1 = fmaxf(rm1, __shfl_xor_sync(0xffffffffu, rm1, 1));
            rm1 = fmaxf(rm1, __shfl_xor_sync(0xffffffffu, rm1, 2));

            float mn0 = fmaxf(m[2 * rg],     rm0);
            float mn1 = fmaxf(m[2 * rg + 1], rm1);
            float a0 = ex2f(m[2 * rg]     - mn0);
            float a1 = ex2f(m[2 * rg + 1] - mn1);
            m[2 * rg] = mn0; m[2 * rg + 1] = mn1;

            float rs0 = 0.f, rs1 = 0.f;
            #pragma unroll
            for (int nt = 0; nt < 8; nt++) {
                s[rg][nt][0] = tf32f(ex2f(s[rg][nt][0] - mn0));
                s[rg][nt][1] = tf32f(ex2f(s[rg][nt][1] - mn0));
                s[rg][nt][2] = tf32f(ex2f(s[rg][nt][2] - mn1));
                s[rg][nt][3] = tf32f(ex2f(s[rg][nt][3] - mn1));
                rs0 += s[rg][nt][0] + s[rg][nt][1];
                rs1 += s[rg][nt][2] + s[rg][nt][3];
            }
            rs0 += __shfl_xor_sync(0xffffffffu, rs0, 1);
            rs0 += __shfl_xor_sync(0xffffffffu, rs0, 2);
            rs1 += __shfl_xor_sync(0xffffffffu, rs1, 1);
            rs1 += __shfl_xor_sync(0xffffffffu, rs1, 2);
            l[2 * rg]     = l[2 * rg]     * a0 + rs0;
            l[2 * rg + 1] = l[2 * rg + 1] * a1 + rs1;

            #pragma unroll
            for (int nt = 0; nt < 8; nt++) {
                o[rg][nt][0] *= a0; o[rg][nt][1] *= a0;
                o[rg][nt][2] *= a1; o[rg][nt][3] *= a1;
            }
        }

        // --- O += P V : P A-frags via register shuffle (no smem) ---
        #pragma unroll
        for (int ks = 0; ks < 8; ks++) {
            uint32_t pa[2][4];
            #pragma unroll
            for (int rg = 0; rg < 2; rg++) {
                float v0  = __shfl_sync(0xffffffffu, s[rg][ks][0], srcA);
                float v1  = __shfl_sync(0xffffffffu, s[rg][ks][1], srcA);
                float v2  = __shfl_sync(0xffffffffu, s[rg][ks][2], srcA);
                float v3  = __shfl_sync(0xffffffffu, s[rg][ks][3], srcA);
                float w0  = __shfl_sync(0xffffffffu, s[rg][ks][0], srcB);
                float w1  = __shfl_sync(0xffffffffu, s[rg][ks][1], srcB);
                float w2  = __shfl_sync(0xffffffffu, s[rg][ks][2], srcB);
                float w3  = __shfl_sync(0xffffffffu, s[rg][ks][3], srcB);
                pa[rg][0] = __float_as_uint(oddq ? v1 : v0);
                pa[rg][1] = __float_as_uint(oddq ? v3 : v2);
                pa[rg][2] = __float_as_uint(oddq ? w1 : w0);
                pa[rg][3] = __float_as_uint(oddq ? w3 : w2);
            }
            #pragma unroll
            for (int ntp = 0; ntp < 4; ntp++) {
                uint32_t vf[4];
                ldm_x4(vf, &Vb[cur][(16 * ntp + brow) * SK + 8 * ks + bcol]);
                mma_tf32(o[0][2 * ntp],     pa[0], vf[0], vf[1]);
                mma_tf32(o[1][2 * ntp],     pa[1], vf[0], vf[1]);
                mma_tf32(o[0][2 * ntp + 1], pa[0], vf[2], vf[3]);
                mma_tf32(o[1][2 * ntp + 1], pa[1], vf[2], vf[3]);
            }
        }
    }

    // --- finalize ---
    float* Og = Out + ((size_t)b * TLEN + (size_t)qb * 64) * HD;
    #pragma unroll
    for (int rg = 0; rg < 2; rg++) {
        float i0 = 1.f / l[2 * rg], i1 = 1.f / l[2 * rg + 1];
        int r = 32 * warp + 16 * rg + g;
        #pragma unroll
        for (int nt = 0; nt < 8; nt++) {
            int c0 = 8 * nt + 2 * qi;
            *(float2*)&Og[(size_t)r * HD + c0] =
                make_float2(o[rg][nt][0] * i0, o[rg][nt][1] * i0);
            *(float2*)&Og[(size_t)(r + 8) * HD + c0] =
                make_float2(o[rg][nt][2] * i1, o[rg][nt][3] * i1);
        }
    }
}

// ---------------------------------------------------------------------------
extern "C" void kernel_launch(void* const* d_in, const int* in_sizes, int n_in,
                              void* d_out, int out_size)
{
    const float* x  = (const float*)d_in[0];
    const float* Wq = (const float*)d_in[1];
    const float* Wk = (const float*)d_in[2];
    const float* Wv = (const float*)d_in[3];
    float* out = (float*)d_out;

    const int smem_qkv  = 64 * 132 * (int)sizeof(float);      // 33792
    const int smem_attn = 4 * 64 * SK * (int)sizeof(float);   // 69632

    cudaFuncSetAttribute(qkv_kernel,
        cudaFuncAttributeMaxDynamicSharedMemorySize, smem_qkv);
    cudaFuncSetAttribute(attn_kernel,
        cudaFuncAttributeMaxDynamicSharedMemorySize, smem_attn);

    qkv_kernel<<<BT / 64, 128, smem_qkv>>>(x, Wq, Wk, Wv);
    attn_kernel<<<dim3(TLEN / 64, NB), 64, smem_attn>>>(out);
}

// round 7
// speedup vs baseline: 3.8879x; 1.2294x over previous
#include <cuda_runtime.h>
#include <math.h>
#include <float.h>
#include <stdint.h>

#define NB    8
#define TLEN  4096
#define BT    (NB * TLEN)   // 32768
#define DM    128
#define HD    64
#define SK    68            // attn smem stride (f32)

// Scratch (tf32-rounded bit patterns stored as float). Q pre-scaled by
// 1/sqrt(128)*log2(e) so attention scores are exp2-domain ready.
__device__ float g_Q[BT * HD];
__device__ float g_K[BT * HD];
__device__ float g_Vt[HD * BT];   // V transposed: [hd][b*T + t]

// ---------------------------------------------------------------------------
// helpers
// ---------------------------------------------------------------------------
__device__ __forceinline__ uint32_t f2tf32(float x) {
    uint32_t r;
    asm("cvt.rna.tf32.f32 %0, %1;" : "=r"(r) : "f"(x));
    return r;
}
__device__ __forceinline__ float tf32f(float x) {
    return __uint_as_float(f2tf32(x));
}
__device__ __forceinline__ float ex2f(float x) {
    float r;
    asm("ex2.approx.ftz.f32 %0, %1;" : "=f"(r) : "f"(x));
    return r;
}
__device__ __forceinline__ void mma_tf32(float* d, const uint32_t* a,
                                         uint32_t b0, uint32_t b1) {
    asm volatile(
        "mma.sync.aligned.m16n8k8.row.col.f32.tf32.tf32.f32 "
        "{%0,%1,%2,%3}, {%4,%5,%6,%7}, {%8,%9}, {%0,%1,%2,%3};\n"
        : "+f"(d[0]), "+f"(d[1]), "+f"(d[2]), "+f"(d[3])
        : "r"(a[0]), "r"(a[1]), "r"(a[2]), "r"(a[3]), "r"(b0), "r"(b1));
}
__device__ __forceinline__ void ldm_x4(uint32_t* r, const float* p) {
    uint32_t a = (uint32_t)__cvta_generic_to_shared(p);
    asm volatile("ldmatrix.sync.aligned.m8n8.x4.shared.b16 {%0,%1,%2,%3}, [%4];"
        : "=r"(r[0]), "=r"(r[1]), "=r"(r[2]), "=r"(r[3]) : "r"(a));
}
__device__ __forceinline__ void cpa16(float* dst, const float* src) {
    uint32_t d = (uint32_t)__cvta_generic_to_shared(dst);
    asm volatile("cp.async.cg.shared.global [%0], [%1], 16;" :: "r"(d), "l"(src));
}
#define CP_COMMIT() asm volatile("cp.async.commit_group;")
#define CP_WAIT0()  asm volatile("cp.async.wait_group 0;" ::: "memory")
#define CP_WAIT1()  asm volatile("cp.async.wait_group 1;" ::: "memory")

// softmax scale folded into Wq: 1/sqrt(128) * log2(e)
#define QSCL (0.08838834764831845f * 1.4426950408889634f)

// ---------------------------------------------------------------------------
// QKV projection on tensor cores. CTA = 64 x-rows, 128 thr = 4 warps.
// Wq columns are pre-multiplied by QSCL so g_Q is exp2-domain-scaled.
// ---------------------------------------------------------------------------
__global__ __launch_bounds__(128) void qkv_kernel(
    const float* __restrict__ x,
    const float* __restrict__ Wq,
    const float* __restrict__ Wk,
    const float* __restrict__ Wv)
{
    extern __shared__ float sm[];
    float* Xs = sm;              // [64][132]

    const int tid  = threadIdx.x;
    const int row0 = blockIdx.x * 64;

    #pragma unroll
    for (int idx = tid; idx < 64 * 32; idx += 128) {
        int r = idx >> 5, c4 = idx & 31;
        float4 v = *(const float4*)(x + (size_t)(row0 + r) * DM + 4 * c4);
        v.x = tf32f(v.x); v.y = tf32f(v.y); v.z = tf32f(v.z); v.w = tf32f(v.w);
        *(float4*)&Xs[r * 132 + 4 * c4] = v;
    }
    __syncthreads();

    const int warp = tid >> 5, lane = tid & 31;
    const int g = lane >> 2, qi = lane & 3;
    const int rowbase = 32 * (warp >> 1);
    const int colbase = 96 * (warp & 1);
    const int arow = ((lane >> 3) & 1) * 8 + (lane & 7);
    const int acol = (lane >> 4) * 4;

    const float* wp[12];
    float wsc[12];
    #pragma unroll
    for (int nt = 0; nt < 12; nt++) {
        int c = colbase + 8 * nt + g;
        const float* Wb = (c < 64) ? Wq : ((c < 128) ? Wk : Wv);
        wp[nt] = Wb + (c & 63);
        wsc[nt] = (c < 64) ? QSCL : 1.0f;
    }

    float s[2][12][4];
    #pragma unroll
    for (int rg = 0; rg < 2; rg++)
        #pragma unroll
        for (int nt = 0; nt < 12; nt++)
            #pragma unroll
            for (int e = 0; e < 4; e++) s[rg][nt][e] = 0.f;

    #pragma unroll
    for (int ks = 0; ks < 16; ks++) {
        uint32_t qa0[4], qa1[4];
        ldm_x4(qa0, &Xs[(rowbase + arow) * 132 + 8 * ks + acol]);
        ldm_x4(qa1, &Xs[(rowbase + 16 + arow) * 132 + 8 * ks + acol]);
        int k0 = (8 * ks + qi) * 64, k1 = (8 * ks + qi + 4) * 64;
        #pragma unroll
        for (int nt = 0; nt < 12; nt++) {
            uint32_t b0 = f2tf32(__ldg(wp[nt] + k0) * wsc[nt]);
            uint32_t b1 = f2tf32(__ldg(wp[nt] + k1) * wsc[nt]);
            mma_tf32(s[0][nt], qa0, b0, b1);
            mma_tf32(s[1][nt], qa1, b0, b1);
        }
    }

    #pragma unroll
    for (int rg = 0; rg < 2; rg++) {
        #pragma unroll
        for (int nt = 0; nt < 12; nt++) {
            int c0 = colbase + 8 * nt + 2 * qi;
            int rA = row0 + rowbase + 16 * rg + g;
            #pragma unroll
            for (int half = 0; half < 2; half++) {
                int r = rA + 8 * half;
                float v0 = tf32f(s[rg][nt][2 * half + 0]);
                float v1 = tf32f(s[rg][nt][2 * half + 1]);
                if (c0 < 64) {
                    *(float2*)&g_Q[(size_t)r * HD + c0] = make_float2(v0, v1);
                } else if (c0 < 128) {
                    *(float2*)&g_K[(size_t)r * HD + (c0 - 64)] = make_float2(v0, v1);
                } else {
                    int h = c0 - 128;
                    g_Vt[(size_t)h * BT + r]       = v0;
                    g_Vt[(size_t)(h + 1) * BT + r] = v1;
                }
            }
        }
    }
}

// ---------------------------------------------------------------------------
// Causal flash attention. 128 threads = 4 warps, BM=64 (16 q-rows/warp),
// BN=64. smem: K double buffer + single V buffer (52.2KB) -> 4 CTAs/SM.
//
// Hazard discipline per iteration kb (cur = kb&1):
//   sync#1 (top, after CP_WAIT0): K(kb) visible; all warps done with
//          V(kb-1), P(kb-1), and cp.async targets free.
//   QK^T reads ALL rows of Kb[cur] -> no warp may write P into Kb[cur]
//          until every warp is past QK.
//   sync#2 (after V-wait): V(kb) visible CTA-wide AND all warps past QK
//          -> P store into Kb[cur] (warp-private rows) is now safe.
//   cp.async groups: A=V(kb), B=K(kb+1). Non-last iter: wait_group 1
//          drains A (B in flight). Last iter: B empty -> wait_group 0.
// ---------------------------------------------------------------------------
__global__ __launch_bounds__(128, 4) void attn_kernel(float* __restrict__ Out)
{
    extern __shared__ float sm[];
    float* Kb[2] = { sm, sm + 64 * SK };
    float* Vb = sm + 2 * 64 * SK;

    const int qb   = 63 - (int)blockIdx.x;  // longest first
    const int b    = blockIdx.y;
    const int tid  = threadIdx.x;
    const int warp = tid >> 5, lane = tid & 31;
    const int g    = lane >> 2, qi = lane & 3;

    const int arow = ((lane >> 3) & 1) * 8 + (lane & 7);
    const int acol = (lane >> 4) * 4;
    const int brow = (lane & 7) + ((lane >> 4) << 3);
    const int bcol = ((lane >> 3) & 1) * 4;

    const float* Kg0 = g_K + (size_t)b * TLEN * HD;
    const float* Vg0 = g_Vt + (size_t)b * TLEN;

    // preload K(0)+V(0) as one group
    #pragma unroll
    for (int idx = tid; idx < 64 * 16; idx += 128) {
        int r = idx >> 4, c4 = (idx & 15) * 4;
        cpa16(&Kb[0][r * SK + c4], Kg0 + (size_t)r * HD + c4);
        cpa16(&Vb[r * SK + c4],    Vg0 + (size_t)r * BT + c4);
    }
    CP_COMMIT();

    // stage Q (pre-scaled tf32) into Kb[1], pull A-fragments
    const float* Qg = g_Q + ((size_t)b * TLEN + (size_t)qb * 64) * HD;
    #pragma unroll
    for (int idx = tid; idx < 64 * 16; idx += 128) {
        int r = idx >> 4, c4 = (idx & 15) * 4;
        *(float4*)&Kb[1][r * SK + c4] = *(const float4*)(Qg + (size_t)r * HD + c4);
    }
    __syncthreads();

    uint32_t qa[8][4];
    #pragma unroll
    for (int ks = 0; ks < 8; ks++)
        ldm_x4(qa[ks], &Kb[1][(16 * warp + arow) * SK + 8 * ks + acol]);

    float o[8][4];
    #pragma unroll
    for (int nt = 0; nt < 8; nt++)
        #pragma unroll
        for (int e = 0; e < 4; e++) o[nt][e] = 0.f;
    float m0 = -1e30f, m1 = -1e30f, l0 = 0.f, l1 = 0.f;

    const int qr = 16 * warp + g;   // thread's first q-row (second is qr+8)

    for (int kb = 0; kb <= qb; kb++) {
        const int cur = kb & 1;

        CP_WAIT0();          // K(kb) (and V(0) on first iter) landed
        __syncthreads();     // sync#1: see hazard discipline above

        // group A: V(kb) into the single V buffer (kb=0 preloaded)
        if (kb > 0) {
            const float* Vg = Vg0 + (size_t)kb * 64;
            #pragma unroll
            for (int idx = tid; idx < 64 * 16; idx += 128) {
                int r = idx >> 4, c4 = (idx & 15) * 4;
                cpa16(&Vb[r * SK + c4], Vg + (size_t)r * BT + c4);
            }
        }
        CP_COMMIT();
        // group B: K(kb+1) into the other K buffer
        if (kb < qb) {
            const float* Kg = Kg0 + (size_t)(kb + 1) * 64 * HD;
            #pragma unroll
            for (int idx = tid; idx < 64 * 16; idx += 128) {
                int r = idx >> 4, c4 = (idx & 15) * 4;
                cpa16(&Kb[1 - cur][r * SK + c4], Kg + (size_t)r * HD + c4);
            }
        }
        CP_COMMIT();

        // --- S = Q K^T (reads all 64 rows of Kb[cur]) ---
        float s[8][4];
        #pragma unroll
        for (int nt = 0; nt < 8; nt++)
            #pragma unroll
            for (int e = 0; e < 4; e++) s[nt][e] = 0.f;

        #pragma unroll
        for (int ks = 0; ks < 8; ks++) {
            #pragma unroll
            for (int ntp = 0; ntp < 4; ntp++) {
                uint32_t kf[4];
                ldm_x4(kf, &Kb[cur][(16 * ntp + brow) * SK + 8 * ks + bcol]);
                mma_tf32(s[2 * ntp],     qa[ks], kf[0], kf[1]);
                mma_tf32(s[2 * ntp + 1], qa[ks], kf[2], kf[3]);
            }
        }

        // --- causal mask: diagonal tile only (scores pre-scaled) ---
        if (kb == qb) {
            #pragma unroll
            for (int nt = 0; nt < 8; nt++) {
                int c0 = 8 * nt + 2 * qi;
                if (c0     > qr    ) s[nt][0] = -1e30f;
                if (c0 + 1 > qr    ) s[nt][1] = -1e30f;
                if (c0     > qr + 8) s[nt][2] = -1e30f;
                if (c0 + 1 > qr + 8) s[nt][3] = -1e30f;
            }
        }

        // --- online softmax (exp2 domain) ---
        float rm0 = -1e30f, rm1 = -1e30f;
        #pragma unroll
        for (int nt = 0; nt < 8; nt++) {
            rm0 = fmaxf(rm0, fmaxf(s[nt][0], s[nt][1]));
            rm1 = fmaxf(rm1, fmaxf(s[nt][2], s[nt][3]));
        }
        rm0 = fmaxf(rm0, __shfl_xor_sync(0xffffffffu, rm0, 1));
        rm0 = fmaxf(rm0, __shfl_xor_sync(0xffffffffu, rm0, 2));
        rm1 = fmaxf(rm1, __shfl_xor_sync(0xffffffffu, rm1, 1));
        rm1 = fmaxf(rm1, __shfl_xor_sync(0xffffffffu, rm1, 2));

        float mn0 = fmaxf(m0, rm0), mn1 = fmaxf(m1, rm1);
        float a0 = ex2f(m0 - mn0), a1 = ex2f(m1 - mn1);
        m0 = mn0; m1 = mn1;

        float rs0 = 0.f, rs1 = 0.f;
        #pragma unroll
        for (int nt = 0; nt < 8; nt++) {
            s[nt][0] = tf32f(ex2f(s[nt][0] - mn0));
            s[nt][1] = tf32f(ex2f(s[nt][1] - mn0));
            s[nt][2] = tf32f(ex2f(s[nt][2] - mn1));
            s[nt][3] = tf32f(ex2f(s[nt][3] - mn1));
            rs0 += s[nt][0] + s[nt][1];
            rs1 += s[nt][2] + s[nt][3];
        }
        rs0 += __shfl_xor_sync(0xffffffffu, rs0, 1);
        rs0 += __shfl_xor_sync(0xffffffffu, rs0, 2);
        rs1 += __shfl_xor_sync(0xffffffffu, rs1, 1);
        rs1 += __shfl_xor_sync(0xffffffffu, rs1, 2);
        l0 = l0 * a0 + rs0;
        l1 = l1 * a1 + rs1;

        #pragma unroll
        for (int nt = 0; nt < 8; nt++) {
            o[nt][0] *= a0; o[nt][1] *= a0;
            o[nt][2] *= a1; o[nt][3] *= a1;
        }

        // V(kb) drain: non-last iter leaves K(kb+1) in flight (wait 1);
        // last iter has empty group B so wait 0 is required.
        if (kb < qb) { CP_WAIT1(); } else { CP_WAIT0(); }
        __syncthreads();   // sync#2: V visible AND all warps past QK reads

        // --- NOW safe: store P into dead K(cur) buffer (per-warp rows) ---
        #pragma unroll
        for (int nt = 0; nt < 8; nt++) {
            *(uint2*)&Kb[cur][qr * SK + 8 * nt + 2 * qi] =
                make_uint2(__float_as_uint(s[nt][0]), __float_as_uint(s[nt][1]));
            *(uint2*)&Kb[cur][(qr + 8) * SK + 8 * nt + 2 * qi] =
                make_uint2(__float_as_uint(s[nt][2]), __float_as_uint(s[nt][3]));
        }
        __syncwarp();

        // --- O += P V ---
        #pragma unroll
        for (int ks = 0; ks < 8; ks++) {
            uint32_t pa[4];
            ldm_x4(pa, &Kb[cur][(16 * warp + arow) * SK + 8 * ks + acol]);
            #pragma unroll
            for (int ntp = 0; ntp < 4; ntp++) {
                uint32_t vf[4];
                ldm_x4(vf, &Vb[(16 * ntp + brow) * SK + 8 * ks + bcol]);
                mma_tf32(o[2 * ntp],     pa, vf[0], vf[1]);
                mma_tf32(o[2 * ntp + 1], pa, vf[2], vf[3]);
            }
        }
    }

    // --- finalize ---
    float* Og = Out + ((size_t)b * TLEN + (size_t)qb * 64) * HD;
    float i0 = 1.f / l0, i1 = 1.f / l1;
    #pragma unroll
    for (int nt = 0; nt < 8; nt++) {
        int c0 = 8 * nt + 2 * qi;
        *(float2*)&Og[(size_t)qr * HD + c0] =
            make_float2(o[nt][0] * i0, o[nt][1] * i0);
        *(float2*)&Og[(size_t)(qr + 8) * HD + c0] =
            make_float2(o[nt][2] * i1, o[nt][3] * i1);
    }
}

// ---------------------------------------------------------------------------
extern "C" void kernel_launch(void* const* d_in, const int* in_sizes, int n_in,
                              void* d_out, int out_size)
{
    const float* x  = (const float*)d_in[0];
    const float* Wq = (const float*)d_in[1];
    const float* Wk = (const float*)d_in[2];
    const float* Wv = (const float*)d_in[3];
    float* out = (float*)d_out;

    const int smem_qkv  = 64 * 132 * (int)sizeof(float);      // 33792
    const int smem_attn = 3 * 64 * SK * (int)sizeof(float);   // 52224

    cudaFuncSetAttribute(qkv_kernel,
        cudaFuncAttributeMaxDynamicSharedMemorySize, smem_qkv);
    cudaFuncSetAttribute(attn_kernel,
        cudaFuncAttributeMaxDynamicSharedMemorySize, smem_attn);

    qkv_kernel<<<BT / 64, 128, smem_qkv>>>(x, Wq, Wk, Wv);
    attn_kernel<<<dim3(TLEN / 64, NB), 128, smem_attn>>>(out);
}

// round 8
// speedup vs baseline: 5.0022x; 1.2866x over previous
#include <cuda_runtime.h>
#include <math.h>
#include <float.h>
#include <stdint.h>

#define NB    8
#define TLEN  4096
#define BT    (NB * TLEN)   // 32768
#define DM    128
#define HD    64
#define SK    68            // attn smem stride (f32)
#define CH    8             // kv tiles per chunk CTA

// Scratch (tf32-rounded bit patterns stored as float). Q pre-scaled by
// 1/sqrt(128)*log2(e) so attention scores are exp2-domain ready.
__device__ float g_Q[BT * HD];
__device__ float g_K[BT * HD];
__device__ float g_Vt[HD * BT];   // V transposed: [hd][b*T + t]

// Split-KV partials: per (qtile, chunk): unnormalized O (64x64), m, l (64)
__device__ float g_Po[NB * 64 * CH * 64 * 64];   // 67 MB
__device__ float g_Pm[NB * 64 * CH * 64];
__device__ float g_Pl[NB * 64 * CH * 64];

// ---------------------------------------------------------------------------
// helpers
// ---------------------------------------------------------------------------
__device__ __forceinline__ uint32_t f2tf32(float x) {
    uint32_t r;
    asm("cvt.rna.tf32.f32 %0, %1;" : "=r"(r) : "f"(x));
    return r;
}
__device__ __forceinline__ float tf32f(float x) {
    return __uint_as_float(f2tf32(x));
}
__device__ __forceinline__ float ex2f(float x) {
    float r;
    asm("ex2.approx.ftz.f32 %0, %1;" : "=f"(r) : "f"(x));
    return r;
}
__device__ __forceinline__ void mma_tf32(float* d, const uint32_t* a,
                                         uint32_t b0, uint32_t b1) {
    asm volatile(
        "mma.sync.aligned.m16n8k8.row.col.f32.tf32.tf32.f32 "
        "{%0,%1,%2,%3}, {%4,%5,%6,%7}, {%8,%9}, {%0,%1,%2,%3};\n"
        : "+f"(d[0]), "+f"(d[1]), "+f"(d[2]), "+f"(d[3])
        : "r"(a[0]), "r"(a[1]), "r"(a[2]), "r"(a[3]), "r"(b0), "r"(b1));
}
__device__ __forceinline__ void ldm_x4(uint32_t* r, const float* p) {
    uint32_t a = (uint32_t)__cvta_generic_to_shared(p);
    asm volatile("ldmatrix.sync.aligned.m8n8.x4.shared.b16 {%0,%1,%2,%3}, [%4];"
        : "=r"(r[0]), "=r"(r[1]), "=r"(r[2]), "=r"(r[3]) : "r"(a));
}
__device__ __forceinline__ void cpa16(float* dst, const float* src) {
    uint32_t d = (uint32_t)__cvta_generic_to_shared(dst);
    asm volatile("cp.async.cg.shared.global [%0], [%1], 16;" :: "r"(d), "l"(src));
}
#define CP_COMMIT() asm volatile("cp.async.commit_group;")
#define CP_WAIT0()  asm volatile("cp.async.wait_group 0;" ::: "memory")
#define CP_WAIT1()  asm volatile("cp.async.wait_group 1;" ::: "memory")

// softmax scale folded into Wq: 1/sqrt(128) * log2(e)
#define QSCL (0.08838834764831845f * 1.4426950408889634f)

// ---------------------------------------------------------------------------
// QKV projection on tensor cores (unchanged from R7).
// ---------------------------------------------------------------------------
__global__ __launch_bounds__(128) void qkv_kernel(
    const float* __restrict__ x,
    const float* __restrict__ Wq,
    const float* __restrict__ Wk,
    const float* __restrict__ Wv)
{
    extern __shared__ float sm[];
    float* Xs = sm;              // [64][132]

    const int tid  = threadIdx.x;
    const int row0 = blockIdx.x * 64;

    #pragma unroll
    for (int idx = tid; idx < 64 * 32; idx += 128) {
        int r = idx >> 5, c4 = idx & 31;
        float4 v = *(const float4*)(x + (size_t)(row0 + r) * DM + 4 * c4);
        v.x = tf32f(v.x); v.y = tf32f(v.y); v.z = tf32f(v.z); v.w = tf32f(v.w);
        *(float4*)&Xs[r * 132 + 4 * c4] = v;
    }
    __syncthreads();

    const int warp = tid >> 5, lane = tid & 31;
    const int g = lane >> 2, qi = lane & 3;
    const int rowbase = 32 * (warp >> 1);
    const int colbase = 96 * (warp & 1);
    const int arow = ((lane >> 3) & 1) * 8 + (lane & 7);
    const int acol = (lane >> 4) * 4;

    const float* wp[12];
    float wsc[12];
    #pragma unroll
    for (int nt = 0; nt < 12; nt++) {
        int c = colbase + 8 * nt + g;
        const float* Wb = (c < 64) ? Wq : ((c < 128) ? Wk : Wv);
        wp[nt] = Wb + (c & 63);
        wsc[nt] = (c < 64) ? QSCL : 1.0f;
    }

    float s[2][12][4];
    #pragma unroll
    for (int rg = 0; rg < 2; rg++)
        #pragma unroll
        for (int nt = 0; nt < 12; nt++)
            #pragma unroll
            for (int e = 0; e < 4; e++) s[rg][nt][e] = 0.f;

    #pragma unroll
    for (int ks = 0; ks < 16; ks++) {
        uint32_t qa0[4], qa1[4];
        ldm_x4(qa0, &Xs[(rowbase + arow) * 132 + 8 * ks + acol]);
        ldm_x4(qa1, &Xs[(rowbase + 16 + arow) * 132 + 8 * ks + acol]);
        int k0 = (8 * ks + qi) * 64, k1 = (8 * ks + qi + 4) * 64;
        #pragma unroll
        for (int nt = 0; nt < 12; nt++) {
            uint32_t b0 = f2tf32(__ldg(wp[nt] + k0) * wsc[nt]);
            uint32_t b1 = f2tf32(__ldg(wp[nt] + k1) * wsc[nt]);
            mma_tf32(s[0][nt], qa0, b0, b1);
            mma_tf32(s[1][nt], qa1, b0, b1);
        }
    }

    #pragma unroll
    for (int rg = 0; rg < 2; rg++) {
        #pragma unroll
        for (int nt = 0; nt < 12; nt++) {
            int c0 = colbase + 8 * nt + 2 * qi;
            int rA = row0 + rowbase + 16 * rg + g;
            #pragma unroll
            for (int half = 0; half < 2; half++) {
                int r = rA + 8 * half;
                float v0 = tf32f(s[rg][nt][2 * half + 0]);
                float v1 = tf32f(s[rg][nt][2 * half + 1]);
                if (c0 < 64) {
                    *(float2*)&g_Q[(size_t)r * HD + c0] = make_float2(v0, v1);
                } else if (c0 < 128) {
                    *(float2*)&g_K[(size_t)r * HD + (c0 - 64)] = make_float2(v0, v1);
                } else {
                    int h = c0 - 128;
                    g_Vt[(size_t)h * BT + r]       = v0;
                    g_Vt[(size_t)(h + 1) * BT + r] = v1;
                }
            }
        }
    }
}

// ---------------------------------------------------------------------------
// Causal flash attention, split-KV. Work unit = (qb, chunk of <=CH kv tiles).
// Per batch: sum over qb of ceil((qb+1)/CH) = 288 units; grid (288, NB).
// Units with nchunks==1 (qb<8) write Out directly; others write partials.
// Inner loop identical to R7 (hazard discipline preserved).
// ---------------------------------------------------------------------------
__global__ __launch_bounds__(128, 4) void attn_kernel(float* __restrict__ Out)
{
    extern __shared__ float sm[];
    float* Kb[2] = { sm, sm + 64 * SK };
    float* Vb = sm + 2 * 64 * SK;

    // map work unit -> (qb, chunk); biggest chunks scheduled first
    const int wu = 287 - (int)blockIdx.x;
    int gI = 0;
    while (wu >= 4 * (gI + 1) * (gI + 2)) gI++;       // offsets[g] = 4g(g+1)
    const int rem   = wu - 4 * gI * (gI + 1);
    const int qb    = 8 * gI + rem / (gI + 1);
    const int chunk = rem % (gI + 1);
    const int nch   = qb / CH + 1;                    // chunks for this qb
    const int t0 = chunk * CH;
    const int t1 = min(t0 + CH, qb + 1);

    const int b    = blockIdx.y;
    const int tid  = threadIdx.x;
    const int warp = tid >> 5, lane = tid & 31;
    const int g    = lane >> 2, qi = lane & 3;

    const int arow = ((lane >> 3) & 1) * 8 + (lane & 7);
    const int acol = (lane >> 4) * 4;
    const int brow = (lane & 7) + ((lane >> 4) << 3);
    const int bcol = ((lane >> 3) & 1) * 4;

    const float* Kg0 = g_K + (size_t)b * TLEN * HD;
    const float* Vg0 = g_Vt + (size_t)b * TLEN;

    // preload K(t0)+V(t0) as one group
    #pragma unroll
    for (int idx = tid; idx < 64 * 16; idx += 128) {
        int r = idx >> 4, c4 = (idx & 15) * 4;
        cpa16(&Kb[0][r * SK + c4], Kg0 + (size_t)(t0 * 64 + r) * HD + c4);
        cpa16(&Vb[r * SK + c4],    Vg0 + (size_t)r * BT + t0 * 64 + c4);
    }
    CP_COMMIT();

    // stage Q (pre-scaled tf32) into Kb[1], pull A-fragments
    const float* Qg = g_Q + ((size_t)b * TLEN + (size_t)qb * 64) * HD;
    #pragma unroll
    for (int idx = tid; idx < 64 * 16; idx += 128) {
        int r = idx >> 4, c4 = (idx & 15) * 4;
        *(float4*)&Kb[1][r * SK + c4] = *(const float4*)(Qg + (size_t)r * HD + c4);
    }
    __syncthreads();

    uint32_t qa[8][4];
    #pragma unroll
    for (int ks = 0; ks < 8; ks++)
        ldm_x4(qa[ks], &Kb[1][(16 * warp + arow) * SK + 8 * ks + acol]);

    float o[8][4];
    #pragma unroll
    for (int nt = 0; nt < 8; nt++)
        #pragma unroll
        for (int e = 0; e < 4; e++) o[nt][e] = 0.f;
    float m0 = -1e30f, m1 = -1e30f, l0 = 0.f, l1 = 0.f;

    const int qr = 16 * warp + g;   // thread's first q-row (second is qr+8)

    for (int kb = t0; kb < t1; kb++) {
        const int cur = (kb - t0) & 1;

        CP_WAIT0();          // K(kb) (and V(t0) on first iter) landed
        __syncthreads();     // sync#1

        // group A: V(kb) (kb=t0 preloaded)
        if (kb > t0) {
            const float* Vg = Vg0 + (size_t)kb * 64;
            #pragma unroll
            for (int idx = tid; idx < 64 * 16; idx += 128) {
                int r = idx >> 4, c4 = (idx & 15) * 4;
                cpa16(&Vb[r * SK + c4], Vg + (size_t)r * BT + c4);
            }
        }
        CP_COMMIT();
        // group B: K(kb+1)
        if (kb + 1 < t1) {
            const float* Kg = Kg0 + (size_t)(kb + 1) * 64 * HD;
            #pragma unroll
            for (int idx = tid; idx < 64 * 16; idx += 128) {
                int r = idx >> 4, c4 = (idx & 15) * 4;
                cpa16(&Kb[1 - cur][r * SK + c4], Kg + (size_t)r * HD + c4);
            }
        }
        CP_COMMIT();

        // --- S = Q K^T (reads all 64 rows of Kb[cur]) ---
        float s[8][4];
        #pragma unroll
        for (int nt = 0; nt < 8; nt++)
            #pragma unroll
            for (int e = 0; e < 4; e++) s[nt][e] = 0.f;

        #pragma unroll
        for (int ks = 0; ks < 8; ks++) {
            #pragma unroll
            for (int ntp = 0; ntp < 4; ntp++) {
                uint32_t kf[4];
                ldm_x4(kf, &Kb[cur][(16 * ntp + brow) * SK + 8 * ks + bcol]);
                mma_tf32(s[2 * ntp],     qa[ks], kf[0], kf[1]);
                mma_tf32(s[2 * ntp + 1], qa[ks], kf[2], kf[3]);
            }
        }

        // --- causal mask: diagonal tile only ---
        if (kb == qb) {
            #pragma unroll
            for (int nt = 0; nt < 8; nt++) {
                int c0 = 8 * nt + 2 * qi;
                if (c0     > qr    ) s[nt][0] = -1e30f;
                if (c0 + 1 > qr    ) s[nt][1] = -1e30f;
                if (c0     > qr + 8) s[nt][2] = -1e30f;
                if (c0 + 1 > qr + 8) s[nt][3] = -1e30f;
            }
        }

        // --- online softmax (exp2 domain) ---
        float rm0 = -1e30f, rm1 = -1e30f;
        #pragma unroll
        for (int nt = 0; nt < 8; nt++) {
            rm0 = fmaxf(rm0, fmaxf(s[nt][0], s[nt][1]));
            rm1 = fmaxf(rm1, fmaxf(s[nt][2], s[nt][3]));
        }
        rm0 = fmaxf(rm0, __shfl_xor_sync(0xffffffffu, rm0, 1));
        rm0 = fmaxf(rm0, __shfl_xor_sync(0xffffffffu, rm0, 2));
        rm1 = fmaxf(rm1, __shfl_xor_sync(0xffffffffu, rm1, 1));
        rm1 = fmaxf(rm1, __shfl_xor_sync(0xffffffffu, rm1, 2));

        float mn0 = fmaxf(m0, rm0), mn1 = fmaxf(m1, rm1);
        float a0 = ex2f(m0 - mn0), a1 = ex2f(m1 - mn1);
        m0 = mn0; m1 = mn1;

        float rs0 = 0.f, rs1 = 0.f;
        #pragma unroll
        for (int nt = 0; nt < 8; nt++) {
            s[nt][0] = tf32f(ex2f(s[nt][0] - mn0));
            s[nt][1] = tf32f(ex2f(s[nt][1] - mn0));
            s[nt][2] = tf32f(ex2f(s[nt][2] - mn1));
            s[nt][3] = tf32f(ex2f(s[nt][3] - mn1));
            rs0 += s[nt][0] + s[nt][1];
            rs1 += s[nt][2] + s[nt][3];
        }
        rs0 += __shfl_xor_sync(0xffffffffu, rs0, 1);
        rs0 += __shfl_xor_sync(0xffffffffu, rs0, 2);
        rs1 += __shfl_xor_sync(0xffffffffu, rs1, 1);
        rs1 += __shfl_xor_sync(0xffffffffu, rs1, 2);
        l0 = l0 * a0 + rs0;
        l1 = l1 * a1 + rs1;

        #pragma unroll
        for (int nt = 0; nt < 8; nt++) {
            o[nt][0] *= a0; o[nt][1] *= a0;
            o[nt][2] *= a1; o[nt][3] *= a1;
        }

        // V drain: last local iter has empty group B -> wait 0; else wait 1.
        if (kb + 1 < t1) { CP_WAIT1(); } else { CP_WAIT0(); }
        __syncthreads();   // sync#2: V visible AND all warps past QK reads

        // --- store P into dead K(cur) buffer (per-warp rows) ---
        #pragma unroll
        for (int nt = 0; nt < 8; nt++) {
            *(uint2*)&Kb[cur][qr * SK + 8 * nt + 2 * qi] =
                make_uint2(__float_as_uint(s[nt][0]), __float_as_uint(s[nt][1]));
            *(uint2*)&Kb[cur][(qr + 8) * SK + 8 * nt + 2 * qi] =
                make_uint2(__float_as_uint(s[nt][2]), __float_as_uint(s[nt][3]));
        }
        __syncwarp();

        // --- O += P V ---
        #pragma unroll
        for (int ks = 0; ks < 8; ks++) {
            uint32_t pa[4];
            ldm_x4(pa, &Kb[cur][(16 * warp + arow) * SK + 8 * ks + acol]);
            #pragma unroll
            for (int ntp = 0; ntp < 4; ntp++) {
                uint32_t vf[4];
                ldm_x4(vf, &Vb[(16 * ntp + brow) * SK + 8 * ks + bcol]);
                mma_tf32(o[2 * ntp],     pa, vf[0], vf[1]);
                mma_tf32(o[2 * ntp + 1], pa, vf[2], vf[3]);
            }
        }
    }

    if (nch == 1) {
        // --- single chunk: finalize directly ---
        float* Og = Out + ((size_t)b * TLEN + (size_t)qb * 64) * HD;
        float i0 = 1.f / l0, i1 = 1.f / l1;
        #pragma unroll
        for (int nt = 0; nt < 8; nt++) {
            int c0 = 8 * nt + 2 * qi;
            *(float2*)&Og[(size_t)qr * HD + c0] =
                make_float2(o[nt][0] * i0, o[nt][1] * i0);
            *(float2*)&Og[(size_t)(qr + 8) * HD + c0] =
                make_float2(o[nt][2] * i1, o[nt][3] * i1);
        }
    } else {
        // --- write unnormalized partial + (m, l) ---
        const size_t pi = ((size_t)(b * 64 + qb) * CH + chunk);
        float* Po = g_Po + pi * 64 * 64;
        #pragma unroll
        for (int nt = 0; nt < 8; nt++) {
            int c0 = 8 * nt + 2 * qi;
            *(float2*)&Po[(size_t)qr * 64 + c0] =
                make_float2(o[nt][0], o[nt][1]);
            *(float2*)&Po[(size_t)(qr + 8) * 64 + c0] =
                make_float2(o[nt][2], o[nt][3]);
        }
        if (qi == 0) {
            g_Pm[pi * 64 + qr]     = m0;
            g_Pl[pi * 64 + qr]     = l0;
            g_Pm[pi * 64 + qr + 8] = m1;
            g_Pl[pi * 64 + qr + 8] = l1;
        }
    }
}

// ---------------------------------------------------------------------------
// Combine partials for qb >= CH. Grid (64-CH, NB), 256 threads.
// Thread handles one row x 16 cols.
// ---------------------------------------------------------------------------
__global__ __launch_bounds__(256) void combine_kernel(float* __restrict__ Out)
{
    const int qb  = CH + (int)blockIdx.x;     // 8..63
    const int b   = blockIdx.y;
    const int nch = qb / CH + 1;
    const int tid = threadIdx.x;
    const int row = tid >> 2;
    const int c0  = (tid & 3) * 16;
    const size_t qt = (size_t)(b * 64 + qb);

    float mv[CH], lv[CH];
    float mmax = -1e30f;
    for (int c = 0; c < nch; c++) {
        mv[c] = g_Pm[(qt * CH + c) * 64 + row];
        lv[c] = g_Pl[(qt * CH + c) * 64 + row];
        mmax = fmaxf(mmax, mv[c]);
    }
    float denom = 0.f;
    float w[CH];
    for (int c = 0; c < nch; c++) {
        w[c] = ex2f(mv[c] - mmax);
        denom += w[c] * lv[c];
    }
    const float inv = 1.f / denom;

    float4 acc[4];
    #pragma unroll
    for (int j = 0; j < 4; j++) acc[j] = make_float4(0.f, 0.f, 0.f, 0.f);

    for (int c = 0; c < nch; c++) {
        const float4* src = (const float4*)(g_Po +
            ((qt * CH + c) * 64 + row) * 64 + c0);
        float wc = w[c];
        #pragma unroll
        for (int j = 0; j < 4; j++) {
            float4 v = src[j];
            acc[j].x += wc * v.x; acc[j].y += wc * v.y;
            acc[j].z += wc * v.z; acc[j].w += wc * v.w;
        }
    }

    float4* dst = (float4*)(Out + ((size_t)b * TLEN + (size_t)qb * 64 + row) * HD + c0);
    #pragma unroll
    for (int j = 0; j < 4; j++) {
        dst[j] = make_float4(acc[j].x * inv, acc[j].y * inv,
                             acc[j].z * inv, acc[j].w * inv);
    }
}

// ---------------------------------------------------------------------------
extern "C" void kernel_launch(void* const* d_in, const int* in_sizes, int n_in,
                              void* d_out, int out_size)
{
    const float* x  = (const float*)d_in[0];
    const float* Wq = (const float*)d_in[1];
    const float* Wk = (const float*)d_in[2];
    const float* Wv = (const float*)d_in[3];
    float* out = (float*)d_out;

    const int smem_qkv  = 64 * 132 * (int)sizeof(float);      // 33792
    const int smem_attn = 3 * 64 * SK * (int)sizeof(float);   // 52224

    cudaFuncSetAttribute(qkv_kernel,
        cudaFuncAttributeMaxDynamicSharedMemorySize, smem_qkv);
    cudaFuncSetAttribute(attn_kernel,
        cudaFuncAttributeMaxDynamicSharedMemorySize, smem_attn);

    qkv_kernel<<<BT / 64, 128, smem_qkv>>>(x, Wq, Wk, Wv);
    attn_kernel<<<dim3(288, NB), 128, smem_attn>>>(out);
    combine_kernel<<<dim3(64 - CH, NB), 256>>>(out);
}